// round 12
// baseline (speedup 1.0000x reference)
#include <cuda_runtime.h>
#include <cuda_fp16.h>
#include <stdint.h>
#include <math.h>

// ---------------- problem constants ----------------
#define NN 4096
#define BB 4
#define EE 1024
#define HH 16
#define DD 512
#define DH 32
#define LL 64
#define RR (NN*BB)   // 16384 rows

// ---------------- gemm geometry ----------------
#define BM 128
#define BN 256
#define BK 64
#define KSTEPS 32                   // K' = 2048 (fp16 2-term split)
#define STAGE_BYTES ((BM+BN)*128)   // 49152
#define NSTAGES 4
#define SMEM_GEMM (NSTAGES*STAGE_BYTES)  // 196608

// ---------------- device scratch ----------------
__device__ __half g_a1[(size_t)RR*2048];      // [query_hi | query_lo]
__device__ __half g_w1[(size_t)3072*1024];    // 6 proj weights, hi only
__device__ __half g_a2[(size_t)RR*2048];      // [ln_hi | ln_lo | grn_hi | grn_lo]
__device__ __half g_w2[(size_t)1024*1024];    // [wol_hi | woc_hi]
__device__ float g_bias1[3072];
__device__ float g_bias2[1024];
__device__ float g_proj[(size_t)6*RR*DD];
__device__ float g_olin[(size_t)RR*DD];
__device__ float g_oloc[(size_t)RR*DD];
__device__ float g_kv    [(size_t)BB*HH*LL*DH*DH];
__device__ float g_kvprev[(size_t)BB*HH*LL*DH*DH];

// ---------------- asm helpers ----------
__device__ __forceinline__ uint32_t smem_u32(const void* p) {
    uint32_t a;
    asm("{ .reg .u64 t; cvta.to.shared.u64 t, %1; cvt.u32.u64 %0, t; }" : "=r"(a) : "l"(p));
    return a;
}
__device__ __forceinline__ void cpasync16(uint32_t s, const void* g) {
    asm volatile("cp.async.cg.shared.global [%0], [%1], 16;" :: "r"(s), "l"(g));
}
#define CP_COMMIT() asm volatile("cp.async.commit_group;" ::: "memory")
#define CP_WAIT0()  asm volatile("cp.async.wait_group 0;"  ::: "memory")

__device__ __forceinline__ void ldsm4(uint32_t* r, uint32_t addr) {
    asm volatile("ldmatrix.sync.aligned.m8n8.x4.shared.b16 {%0,%1,%2,%3}, [%4];"
        : "=r"(r[0]), "=r"(r[1]), "=r"(r[2]), "=r"(r[3]) : "r"(addr));
}
__device__ __forceinline__ void mma_f16(float* c, const uint32_t* a,
                                        uint32_t b0, uint32_t b1) {
    asm volatile(
        "mma.sync.aligned.m16n8k16.row.col.f32.f16.f16.f32 "
        "{%0,%1,%2,%3}, {%4,%5,%6,%7}, {%8,%9}, {%0,%1,%2,%3};"
        : "+f"(c[0]), "+f"(c[1]), "+f"(c[2]), "+f"(c[3])
        : "r"(a[0]), "r"(a[1]), "r"(a[2]), "r"(a[3]), "r"(b0), "r"(b1));
}

__device__ __forceinline__ float gelu_tanh(float x) {
    float x3 = x*x*x;
    return 0.5f*x*(1.0f + tanhf(0.7978845608028654f*(x + 0.044715f*x3)));
}
__device__ __forceinline__ void split_f16(float x, __half& hi, __half& lo) {
    hi = __float2half(x);
    lo = __float2half(x - __half2float(hi));
}
__device__ __forceinline__ uint32_t swz128(int row) {
    return (uint32_t)(row*128) ^ (((uint32_t)row & 7u) << 4);
}
__device__ __forceinline__ void seg_off(int gemmid, int ks, int& aoff, int& boff) {
    if (gemmid == 0) {
        int seg = ks >> 4, ko = (ks & 15)*64;
        aoff = ko + (seg ? 1024 : 0);
        boff = ko;
    } else {
        int seg = ks >> 3, ko = (ks & 7)*64;
        aoff = seg*512 + ko;
        boff = (seg >= 2 ? 512 : 0) + ko;
    }
}

// =======================================================================
//   fp16 mma.sync GEMM (unchanged)
// =======================================================================
__global__ __launch_bounds__(512, 1)
void gemm_tc(int gemmid, float* __restrict__ outp)
{
    extern __shared__ char smem[];
    const uint32_t sb = smem_u32(smem);
    const int tid = threadIdx.x;
    const int mbase = blockIdx.y * BM;
    const int nbase = blockIdx.x * BN;
    const __half* __restrict__ Ap = gemmid ? g_a2 : g_a1;
    const __half* __restrict__ Bp = gemmid ? g_w2 : g_w1;

    float acc[2][8][4];
    #pragma unroll
    for (int i = 0; i < 2; i++)
        #pragma unroll
        for (int j = 0; j < 8; j++)
            #pragma unroll
            for (int q = 0; q < 4; q++) acc[i][j][q] = 0.f;

    const int ldA_row0 = tid >> 3,          ldA_row1 = (tid + 512) >> 3;
    const int ldB_row0 = tid >> 3,          ldB_row1 = (tid + 512) >> 3;
    const int ldB_row2 = (tid + 1024) >> 3, ldB_row3 = (tid + 1536) >> 3;
    const int ld_ch = tid & 7;
    const uint32_t chx = (uint32_t)ld_ch << 4;
    const uint32_t sA0 = swz128(ldA_row0) ^ chx;
    const uint32_t sA1 = swz128(ldA_row1) ^ chx;
    const uint32_t sB0 = (uint32_t)(BM*128) + (swz128(ldB_row0) ^ chx);
    const uint32_t sB1 = (uint32_t)(BM*128) + (swz128(ldB_row1) ^ chx);
    const uint32_t sB2 = (uint32_t)(BM*128) + (swz128(ldB_row2) ^ chx);
    const uint32_t sB3 = (uint32_t)(BM*128) + (swz128(ldB_row3) ^ chx);

    auto load_stage = [&](uint32_t sst, int aoff, int boff) {
        cpasync16(sst + sA0, Ap + (size_t)(mbase + ldA_row0)*2048 + aoff + ld_ch*8);
        cpasync16(sst + sA1, Ap + (size_t)(mbase + ldA_row1)*2048 + aoff + ld_ch*8);
        cpasync16(sst + sB0, Bp + (size_t)(nbase + ldB_row0)*1024 + boff + ld_ch*8);
        cpasync16(sst + sB1, Bp + (size_t)(nbase + ldB_row1)*1024 + boff + ld_ch*8);
        cpasync16(sst + sB2, Bp + (size_t)(nbase + ldB_row2)*1024 + boff + ld_ch*8);
        cpasync16(sst + sB3, Bp + (size_t)(nbase + ldB_row3)*1024 + boff + ld_ch*8);
    };

    const int lane = tid & 31, wid = tid >> 5;
    const int m0 = (wid & 3) * 32;
    const int n0 = (wid >> 2) * 64;

    uint32_t aBase[2], bBase[4];
    #pragma unroll
    for (int mt = 0; mt < 2; mt++)
        aBase[mt] = swz128(m0 + mt*16 + (lane & 15));
    #pragma unroll
    for (int p = 0; p < 4; p++)
        bBase[p] = (uint32_t)(BM*128) + swz128(n0 + p*16 + (lane & 15));
    const uint32_t kqSel = (uint32_t)(lane >> 4) << 4;

    auto compute_pair = [&](uint32_t sS0, uint32_t sS1) {
        uint32_t aCur[2][4], aNxt[2][4], bCur[4], bNxt[4];
        const uint32_t sArr2[2] = {sS0, sS1};
        {
            ldsm4(aCur[0], sS0 + (aBase[0] ^ kqSel));
            ldsm4(aCur[1], sS0 + (aBase[1] ^ kqSel));
            ldsm4(bCur,    sS0 + (bBase[0] ^ kqSel));
        }
        #pragma unroll
        for (int sl = 0; sl < 8; sl++) {
            uint32_t sS = sArr2[sl >> 2];
            uint32_t kx = ((uint32_t)((sl & 3) * 2) << 4) ^ kqSel;
            #pragma unroll
            for (int p = 0; p < 4; p++) {
                if (p < 3) {
                    ldsm4(bNxt, sS + (bBase[p+1] ^ kx));
                } else if (sl < 7) {
                    uint32_t sS2 = sArr2[(sl+1) >> 2];
                    uint32_t kx2 = ((uint32_t)(((sl+1) & 3) * 2) << 4) ^ kqSel;
                    ldsm4(aNxt[0], sS2 + (aBase[0] ^ kx2));
                    ldsm4(aNxt[1], sS2 + (aBase[1] ^ kx2));
                    ldsm4(bNxt,    sS2 + (bBase[0] ^ kx2));
                }
                #pragma unroll
                for (int mt = 0; mt < 2; mt++) {
                    mma_f16(acc[mt][2*p],   aCur[mt], bCur[0], bCur[2]);
                    mma_f16(acc[mt][2*p+1], aCur[mt], bCur[1], bCur[3]);
                }
                #pragma unroll
                for (int q = 0; q < 4; q++) bCur[q] = bNxt[q];
            }
            #pragma unroll
            for (int mt = 0; mt < 2; mt++)
                #pragma unroll
                for (int q = 0; q < 4; q++) aCur[mt][q] = aNxt[mt][q];
        }
    };

    {
        int ao, bo;
        seg_off(gemmid, 0, ao, bo); load_stage(sb, ao, bo); CP_COMMIT();
        seg_off(gemmid, 1, ao, bo); load_stage(sb + STAGE_BYTES, ao, bo); CP_COMMIT();
    }

    for (int ks = 0; ks < KSTEPS; ks += 2) {
        CP_WAIT0();
        __syncthreads();
        if (ks + 3 < KSTEPS) {
            int ao, bo;
            seg_off(gemmid, ks + 2, ao, bo);
            load_stage(sb + (uint32_t)(((ks + 2) & 3) * STAGE_BYTES), ao, bo);
            CP_COMMIT();
            seg_off(gemmid, ks + 3, ao, bo);
            load_stage(sb + (uint32_t)(((ks + 3) & 3) * STAGE_BYTES), ao, bo);
            CP_COMMIT();
        }
        compute_pair(sb + (uint32_t)((ks & 3) * STAGE_BYTES),
                     sb + (uint32_t)(((ks + 1) & 3) * STAGE_BYTES));
    }

    const int r_lo  = mbase + m0 + (lane >> 2);
    const int cbase = nbase + n0 + (lane & 3)*2;
    #pragma unroll
    for (int mt = 0; mt < 2; mt++) {
        #pragma unroll
        for (int nt = 0; nt < 8; nt++) {
            int col = cbase + nt*8;
            int row0 = r_lo + mt*16;
            float v0 = acc[mt][nt][0], v1 = acc[mt][nt][1];
            float v2 = acc[mt][nt][2], v3 = acc[mt][nt][3];
            if (gemmid == 0) {
                float b0 = g_bias1[col], b1 = g_bias1[col+1];
                v0 += b0; v1 += b1; v2 += b0; v3 += b1;
                int proj = col >> 9, lc = col & 511;
                if (proj < 2) {
                    v0 = gelu_tanh(v0); v1 = gelu_tanh(v1);
                    v2 = gelu_tanh(v2); v3 = gelu_tanh(v3);
                }
                float* base = g_proj + (size_t)proj * ((size_t)RR*DD);
                *reinterpret_cast<float2*>(base + (size_t)row0*DD + lc)
                    = make_float2(v0, v1);
                *reinterpret_cast<float2*>(base + (size_t)(row0+8)*DD + lc)
                    = make_float2(v2, v3);
            } else {
                float b0 = g_bias2[col], b1 = g_bias2[col+1];
                *reinterpret_cast<float2*>(outp + (size_t)row0*1024 + col)
                    = make_float2(0.5f*v0 + b0, 0.5f*v1 + b1);
                *reinterpret_cast<float2*>(outp + (size_t)(row0+8)*1024 + col)
                    = make_float2(0.5f*v2 + b0, 0.5f*v3 + b1);
            }
        }
    }
}

// =======================================================================
//   conv_main: conv_a1 (16384 blocks) + conv_w1b (12288 blocks) fused
// =======================================================================
__global__ void conv_main(const float* __restrict__ query,
                          const float* __restrict__ w0, const float* __restrict__ w1,
                          const float* __restrict__ w2, const float* __restrict__ w3,
                          const float* __restrict__ w4, const float* __restrict__ w5,
                          const float* __restrict__ b0, const float* __restrict__ b1,
                          const float* __restrict__ b2, const float* __restrict__ b3,
                          const float* __restrict__ b4, const float* __restrict__ b5,
                          const float* __restrict__ bo_lin, const float* __restrict__ bo_loc)
{
    int bid = blockIdx.x;
    if (bid < 16384) {
        size_t i4 = ((size_t)bid * 256 + threadIdx.x) * 4;
        int r = (int)(i4 >> 10), c = (int)(i4 & 1023);
        float4 v = *reinterpret_cast<const float4*>(query + i4);
        __half hi[4], lo[4];
        split_f16(v.x, hi[0], lo[0]); split_f16(v.y, hi[1], lo[1]);
        split_f16(v.z, hi[2], lo[2]); split_f16(v.w, hi[3], lo[3]);
        __half* dst = g_a1 + (size_t)r*2048 + c;
        *reinterpret_cast<uint2*>(dst)        = *reinterpret_cast<uint2*>(hi);
        *reinterpret_cast<uint2*>(dst + 1024) = *reinterpret_cast<uint2*>(lo);
    } else {
        size_t i = (size_t)(bid - 16384) * 256 + threadIdx.x;   // 3072*1024
        int n = (int)(i >> 10), k = (int)(i & 1023);
        int proj = n >> 9, rloc = n & 511;
        const float* src;
        switch (proj) {
            case 0: src = w0; break; case 1: src = w1; break; case 2: src = w2; break;
            case 3: src = w3; break; case 4: src = w4; break; default: src = w5; break;
        }
        g_w1[(size_t)n*1024 + k] = __float2half(src[(size_t)rloc*1024 + k]);
        if (i < 3072) {
            int proj2 = (int)i >> 9, lc = (int)i & 511;
            const float* bs;
            switch (proj2) {
                case 0: bs = b0; break; case 1: bs = b1; break; case 2: bs = b2; break;
                case 3: bs = b3; break; case 4: bs = b4; break; default: bs = b5; break;
            }
            g_bias1[i] = bs[lc];
            if (i < 1024) g_bias2[i] = 0.5f * (bo_lin[i] + bo_loc[i]);
        }
    }
}

__global__ void conv_w2(const float* __restrict__ wo_lin, const float* __restrict__ wo_loc)
{
    size_t i = (size_t)blockIdx.x * 256 + threadIdx.x;
    int n = (int)(i >> 9), k = (int)(i & 511);
    g_w2[(size_t)n*1024 + k]       = __float2half(wo_lin[(size_t)n*512 + k]);
    g_w2[(size_t)n*1024 + 512 + k] = __float2half(wo_loc[(size_t)n*512 + k]);
}

// =======================================================================
//   attn_lk: local attention (blocks 0..4095) + kv state (4096..8191)
//   vectorized smem access (float4 broadcast S/q reads, float2 v)
// =======================================================================
__global__ __launch_bounds__(256)
void attn_lk()
{
    __shared__ float sm[2304*2 + 2176 + 4352];   // qs[64][36] ks[64][36] vs[64][34] S[64][68]
    float (*qs)[36] = (float(*)[36])sm;
    float (*ks)[36] = (float(*)[36])(sm + 2304);
    float (*vs)[34] = (float(*)[34])(sm + 4608);
    float (*S )[68] = (float(*)[68])(sm + 6784);

    int bid = blockIdx.x;
    int tid = threadIdx.x;

    if (bid < 4096) {
        // ------------- local branch: o = (relu(q k^T) * tril) @ v -------------
        int z = bid;
        int l = z & 63, h = (z >> 6) & 15, b = z >> 10;
        const float* Q = g_proj + (size_t)3*RR*DD;
        const float* K = g_proj + (size_t)4*RR*DD;
        const float* V = g_proj + (size_t)5*RR*DD;

        for (int idx = tid; idx < 64*32; idx += 256) {
            int c = idx >> 5, dh = idx & 31;
            size_t off = ((size_t)((l*64 + c)*BB + b))*DD + h*32 + dh;
            qs[c][dh] = Q[off]; ks[c][dh] = K[off]; vs[c][dh] = V[off];
        }
        __syncthreads();

        {   // S-loop: 4x4 tiles, d vectorized by 4
            int tr = tid >> 4, tc = tid & 15;
            int c0 = tr*4, j0 = tc*4;
            float s[4][4] = {{0.f}};
            if (tc <= tr) {
                #pragma unroll
                for (int d4 = 0; d4 < 32; d4 += 4) {
                    float4 rq[4], rk[4];
                    #pragma unroll
                    for (int i = 0; i < 4; i++)
                        rq[i] = *reinterpret_cast<const float4*>(&qs[c0+i][d4]);
                    #pragma unroll
                    for (int j = 0; j < 4; j++)
                        rk[j] = *reinterpret_cast<const float4*>(&ks[j0+j][d4]);
                    #pragma unroll
                    for (int i = 0; i < 4; i++)
                        #pragma unroll
                        for (int j = 0; j < 4; j++)
                            s[i][j] += rq[i].x*rk[j].x + rq[i].y*rk[j].y
                                     + rq[i].z*rk[j].z + rq[i].w*rk[j].w;
                }
            }
            #pragma unroll
            for (int i = 0; i < 4; i++)
                #pragma unroll
                for (int j = 0; j < 4; j++)
                    S[c0+i][j0+j] = (j0+j <= c0+i) ? fmaxf(s[i][j], 0.f) : 0.f;
        }
        __syncthreads();

        {   // O-loop: 4x2 tiles, j vectorized by 4, S reads broadcast
            int cg = tid >> 4, dg = tid & 15;
            int c0 = cg*4, dh0 = dg*2;
            float o[4][2] = {{0.f}};
            #pragma unroll
            for (int j4 = 0; j4 < 64; j4 += 4) {
                float4 s4[4]; float2 v2[4];
                #pragma unroll
                for (int i = 0; i < 4; i++)
                    s4[i] = *reinterpret_cast<const float4*>(&S[c0+i][j4]);
                #pragma unroll
                for (int jj = 0; jj < 4; jj++)
                    v2[jj] = *reinterpret_cast<const float2*>(&vs[j4+jj][dh0]);
                #pragma unroll
                for (int i = 0; i < 4; i++) {
                    o[i][0] += s4[i].x*v2[0].x + s4[i].y*v2[1].x
                             + s4[i].z*v2[2].x + s4[i].w*v2[3].x;
                    o[i][1] += s4[i].x*v2[0].y + s4[i].y*v2[1].y
                             + s4[i].z*v2[2].y + s4[i].w*v2[3].y;
                }
            }
            #pragma unroll
            for (int i = 0; i < 4; i++) {
                size_t off = ((size_t)((l*64 + c0+i)*BB + b))*DD + h*32 + dh0;
                *reinterpret_cast<float2*>(g_oloc + off) = make_float2(o[i][0], o[i][1]);
            }
        }
    } else {
        // ------------- kv branch: kv[d][e] = sum_c k[c][d] v[c][e] -------------
        int z = bid - 4096;
        int l = z & 63, h = (z >> 6) & 15, b = z >> 10;
        const float* K = g_proj + (size_t)1*RR*DD;
        const float* V = g_proj + (size_t)2*RR*DD;

        for (int idx = tid; idx < 64*32; idx += 256) {
            int c = idx >> 5, dh = idx & 31;
            size_t off = ((size_t)((l*64 + c)*BB + b))*DD + h*32 + dh;
            qs[c][dh] = K[off]; vs[c][dh] = V[off];
        }
        __syncthreads();

        int d0 = (tid >> 4)*2, e0 = (tid & 15)*2;
        float s00 = 0.f, s01 = 0.f, s10 = 0.f, s11 = 0.f;
        #pragma unroll 8
        for (int c = 0; c < 64; c++) {
            float k0 = qs[c][d0], k1 = qs[c][d0+1];
            float2 v2 = *reinterpret_cast<const float2*>(&vs[c][e0]);
            s00 += k0*v2.x; s01 += k0*v2.y;
            s10 += k1*v2.x; s11 += k1*v2.y;
        }
        float* dst = g_kv + (size_t)z*1024;
        *reinterpret_cast<float2*>(dst + (d0  )*32 + e0) = make_float2(s00, s01);
        *reinterpret_cast<float2*>(dst + (d0+1)*32 + e0) = make_float2(s10, s11);
    }
}

__global__ __launch_bounds__(256)
void kv_cumsum_kernel()
{
    int bh = blockIdx.x >> 2;
    int j  = (blockIdx.x & 3) * 256 + threadIdx.x;
    const float* src = g_kv     + (size_t)bh*LL*1024 + j;
    float*       dst = g_kvprev + (size_t)bh*LL*1024 + j;
    float acc = 0.f;
    #pragma unroll 8
    for (int l = 0; l < LL; l++) {
        dst[l*1024] = acc;
        acc += src[l*1024];
    }
}

// =======================================================================
//   attn_lin: o = (q k^T * tril) @ v + q @ kv_prev  (vectorized)
// =======================================================================
__global__ __launch_bounds__(256)
void attn_lin_kernel()
{
    __shared__ float sm[2304*2 + 2176 + 1088 + 4352]; // qs ks vs kvp S  (48896 B)
    float (*qs )[36] = (float(*)[36])sm;
    float (*ks )[36] = (float(*)[36])(sm + 2304);
    float (*vs )[34] = (float(*)[34])(sm + 4608);
    float (*kvp)[34] = (float(*)[34])(sm + 6784);
    float (*S  )[68] = (float(*)[68])(sm + 7872);

    int z = blockIdx.x;
    int l = z & 63, h = (z >> 6) & 15, b = z >> 10;
    int tid = threadIdx.x;
    const float* Q = g_proj;
    const float* K = g_proj + (size_t)1*RR*DD;
    const float* V = g_proj + (size_t)2*RR*DD;

    for (int idx = tid; idx < 64*32; idx += 256) {
        int c = idx >> 5, dh = idx & 31;
        size_t off = ((size_t)((l*64 + c)*BB + b))*DD + h*32 + dh;
        qs[c][dh] = Q[off]; ks[c][dh] = K[off]; vs[c][dh] = V[off];
    }
    for (int idx = tid; idx < 32*32; idx += 256)
        kvp[idx >> 5][idx & 31] = g_kvprev[(size_t)z*1024 + idx];
    __syncthreads();

    {   // S-loop
        int tr = tid >> 4, tc = tid & 15;
        int c0 = tr*4, j0 = tc*4;
        float s[4][4] = {{0.f}};
        if (tc <= tr) {
            #pragma unroll
            for (int d4 = 0; d4 < 32; d4 += 4) {
                float4 rq[4], rk[4];
                #pragma unroll
                for (int i = 0; i < 4; i++)
                    rq[i] = *reinterpret_cast<const float4*>(&qs[c0+i][d4]);
                #pragma unroll
                for (int j = 0; j < 4; j++)
                    rk[j] = *reinterpret_cast<const float4*>(&ks[j0+j][d4]);
                #pragma unroll
                for (int i = 0; i < 4; i++)
                    #pragma unroll
                    for (int j = 0; j < 4; j++)
                        s[i][j] += rq[i].x*rk[j].x + rq[i].y*rk[j].y
                                 + rq[i].z*rk[j].z + rq[i].w*rk[j].w;
            }
        }
        #pragma unroll
        for (int i = 0; i < 4; i++)
            #pragma unroll
            for (int j = 0; j < 4; j++)
                S[c0+i][j0+j] = (j0+j <= c0+i) ? s[i][j] : 0.f;
    }
    __syncthreads();

    {   // O-loop: S@v + q@kvp
        int cg = tid >> 4, dg = tid & 15;
        int c0 = cg*4, dh0 = dg*2;
        float o[4][2] = {{0.f}};
        #pragma unroll
        for (int j4 = 0; j4 < 64; j4 += 4) {
            float4 s4[4]; float2 v2[4];
            #pragma unroll
            for (int i = 0; i < 4; i++)
                s4[i] = *reinterpret_cast<const float4*>(&S[c0+i][j4]);
            #pragma unroll
            for (int jj = 0; jj < 4; jj++)
                v2[jj] = *reinterpret_cast<const float2*>(&vs[j4+jj][dh0]);
            #pragma unroll
            for (int i = 0; i < 4; i++) {
                o[i][0] += s4[i].x*v2[0].x + s4[i].y*v2[1].x
                         + s4[i].z*v2[2].x + s4[i].w*v2[3].x;
                o[i][1] += s4[i].x*v2[0].y + s4[i].y*v2[1].y
                         + s4[i].z*v2[2].y + s4[i].w*v2[3].y;
            }
        }
        #pragma unroll
        for (int d4 = 0; d4 < 32; d4 += 4) {
            float4 q4[4]; float2 p2[4];
            #pragma unroll
            for (int i = 0; i < 4; i++)
                q4[i] = *reinterpret_cast<const float4*>(&qs[c0+i][d4]);
            #pragma unroll
            for (int dd = 0; dd < 4; dd++)
                p2[dd] = *reinterpret_cast<const float2*>(&kvp[d4+dd][dh0]);
            #pragma unroll
            for (int i = 0; i < 4; i++) {
                o[i][0] += q4[i].x*p2[0].x + q4[i].y*p2[1].x
                         + q4[i].z*p2[2].x + q4[i].w*p2[3].x;
                o[i][1] += q4[i].x*p2[0].y + q4[i].y*p2[1].y
                         + q4[i].z*p2[2].y + q4[i].w*p2[3].y;
            }
        }
        #pragma unroll
        for (int i = 0; i < 4; i++) {
            size_t off = ((size_t)((l*64 + c0+i)*BB + b))*DD + h*32 + dh0;
            *reinterpret_cast<float2*>(g_olin + off) = make_float2(o[i][0], o[i][1]);
        }
    }
}

// ---------------- norms — warp-per-row ----------------
__global__ __launch_bounds__(256)
void norm_kernel(const float* __restrict__ ln_g, const float* __restrict__ ln_b,
                 const float* __restrict__ gsc,  const float* __restrict__ ggt)
{
    int warp = (blockIdx.x << 3) | (threadIdx.x >> 5);
    int lane = threadIdx.x & 31;
    __half* a2 = g_a2 + (size_t)warp*2048;

    const float* xl = g_olin + (size_t)warp*DD;
    float xa[16];
    float sum = 0.f;
    #pragma unroll
    for (int k = 0; k < 16; k++) { xa[k] = xl[lane + 32*k]; sum += xa[k]; }
    #pragma unroll
    for (int o = 16; o > 0; o >>= 1) sum += __shfl_xor_sync(0xffffffffu, sum, o);
    float mu = sum * (1.0f/512.0f);
    float vsum = 0.f;
    #pragma unroll
    for (int k = 0; k < 16; k++) { float d = xa[k] - mu; vsum += d*d; }
    #pragma unroll
    for (int o = 16; o > 0; o >>= 1) vsum += __shfl_xor_sync(0xffffffffu, vsum, o);
    float rs = rsqrtf(vsum * (1.0f/512.0f) + 1e-5f);
    #pragma unroll
    for (int k = 0; k < 16; k++) {
        int c = lane + 32*k;
        float y = (xa[k] - mu)*rs*ln_g[c] + ln_b[c];
        __half hi, lo; split_f16(y, hi, lo);
        a2[c] = hi; a2[512 + c] = lo;
    }

    const float* xo = g_oloc + (size_t)warp*DD;
    float ms = 0.f;
    #pragma unroll
    for (int k = 0; k < 16; k++) { xa[k] = xo[lane + 32*k]; ms += xa[k]*xa[k]; }
    #pragma unroll
    for (int o = 16; o > 0; o >>= 1) ms += __shfl_xor_sync(0xffffffffu, ms, o);
    float inv = rsqrtf(ms * (1.0f/512.0f) + 1e-8f);
    #pragma unroll
    for (int k = 0; k < 16; k++) {
        int c = lane + 32*k;
        float sg = 1.0f/(1.0f + expf(-ggt[c]*xa[k]));
        float zv = xa[k]*inv*gsc[c]*sg;
        __half hi, lo; split_f16(zv, hi, lo);
        a2[1024 + c] = hi; a2[1536 + c] = lo;
    }
}

// =======================================================================
//   launch  (attn_lk at idx 3 -> profiled)
// =======================================================================
extern "C" void kernel_launch(void* const* d_in, const int* in_sizes, int n_in,
                              void* d_out, int out_size)
{
    const float* query   = (const float*)d_in[0];
    const float* wq_lin  = (const float*)d_in[1];
    const float* bq_lin  = (const float*)d_in[2];
    const float* wk_lin  = (const float*)d_in[3];
    const float* bk_lin  = (const float*)d_in[4];
    const float* wv_lin  = (const float*)d_in[5];
    const float* bv_lin  = (const float*)d_in[6];
    const float* wo_lin  = (const float*)d_in[7];
    const float* bo_lin  = (const float*)d_in[8];
    const float* wq_loc  = (const float*)d_in[9];
    const float* bq_loc  = (const float*)d_in[10];
    const float* wk_loc  = (const float*)d_in[11];
    const float* bk_loc  = (const float*)d_in[12];
    const float* wv_loc  = (const float*)d_in[13];
    const float* bv_loc  = (const float*)d_in[14];
    const float* wo_loc  = (const float*)d_in[15];
    const float* bo_loc  = (const float*)d_in[16];
    const float* ln_g    = (const float*)d_in[17];
    const float* ln_b    = (const float*)d_in[18];
    const float* grn_s   = (const float*)d_in[19];
    const float* grn_g   = (const float*)d_in[20];
    float* out = (float*)d_out;

    cudaFuncSetAttribute(gemm_tc, cudaFuncAttributeMaxDynamicSharedMemorySize, SMEM_GEMM);

    // 0: fused conversions (query split + w1 + biases)
    conv_main<<<16384 + 12288, 256>>>(query,
        wq_lin, wk_lin, wv_lin, wq_loc, wk_loc, wv_loc,
        bq_lin, bk_lin, bv_lin, bq_loc, bk_loc, bv_loc, bo_lin, bo_loc);
    // 1
    conv_w2<<<2048, 256>>>(wo_lin, wo_loc);
    // 2: fused input projections
    gemm_tc<<<dim3(3072/BN, RR/BM), 512, SMEM_GEMM>>>(0, nullptr);
    // 3: local attention + kv state (profiled)
    attn_lk<<<8192, 256>>>();
    // 4
    kv_cumsum_kernel<<<BB*HH*4, 256>>>();
    // 5
    attn_lin_kernel<<<BB*HH*LL, 256>>>();
    // 6
    norm_kernel<<<RR/8, 256>>>(ln_g, ln_b, grn_s, grn_g);
    // 7: fused output projections
    gemm_tc<<<dim3(1024/BN, RR/BM), 512, SMEM_GEMM>>>(1, out);
}

// round 13
// speedup vs baseline: 1.0464x; 1.0464x over previous
#include <cuda_runtime.h>
#include <cuda_fp16.h>
#include <stdint.h>
#include <math.h>

// ---------------- problem constants ----------------
#define NN 4096
#define BB 4
#define EE 1024
#define HH 16
#define DD 512
#define DH 32
#define LL 64
#define RR (NN*BB)   // 16384 rows

// ---------------- gemm geometry ----------------
#define BM 128
#define BN 256
#define BK 64
#define KSTEPS 32                   // K' = 2048 (fp16 2-term split)
#define STAGE_BYTES ((BM+BN)*128)   // 49152
#define NSTAGES 4
#define SMEM_GEMM (NSTAGES*STAGE_BYTES)  // 196608

// ---------------- device scratch ----------------
__device__ __half g_a1[(size_t)RR*2048];      // [query_hi | query_lo]
__device__ __half g_w1[(size_t)3072*1024];    // 6 proj weights, hi only
__device__ __half g_a2[(size_t)RR*2048];      // [ln_hi | ln_lo | grn_hi | grn_lo]
__device__ __half g_w2[(size_t)1024*1024];    // [wol_hi | woc_hi]
__device__ float g_bias1[3072];
__device__ float g_bias2[1024];
__device__ float g_proj[(size_t)6*RR*DD];
__device__ float g_olin[(size_t)RR*DD];
__device__ float g_oloc[(size_t)RR*DD];
__device__ float g_kv    [(size_t)BB*HH*LL*DH*DH];
__device__ float g_kvprev[(size_t)BB*HH*LL*DH*DH];

// ---------------- asm helpers ----------
__device__ __forceinline__ uint32_t smem_u32(const void* p) {
    uint32_t a;
    asm("{ .reg .u64 t; cvta.to.shared.u64 t, %1; cvt.u32.u64 %0, t; }" : "=r"(a) : "l"(p));
    return a;
}
__device__ __forceinline__ void cpasync16(uint32_t s, const void* g) {
    asm volatile("cp.async.cg.shared.global [%0], [%1], 16;" :: "r"(s), "l"(g));
}
#define CP_COMMIT() asm volatile("cp.async.commit_group;" ::: "memory")
#define CP_WAIT0()  asm volatile("cp.async.wait_group 0;"  ::: "memory")

__device__ __forceinline__ void ldsm4(uint32_t* r, uint32_t addr) {
    asm volatile("ldmatrix.sync.aligned.m8n8.x4.shared.b16 {%0,%1,%2,%3}, [%4];"
        : "=r"(r[0]), "=r"(r[1]), "=r"(r[2]), "=r"(r[3]) : "r"(addr));
}
__device__ __forceinline__ void mma_f16(float* c, const uint32_t* a,
                                        uint32_t b0, uint32_t b1) {
    asm volatile(
        "mma.sync.aligned.m16n8k16.row.col.f32.f16.f16.f32 "
        "{%0,%1,%2,%3}, {%4,%5,%6,%7}, {%8,%9}, {%0,%1,%2,%3};"
        : "+f"(c[0]), "+f"(c[1]), "+f"(c[2]), "+f"(c[3])
        : "r"(a[0]), "r"(a[1]), "r"(a[2]), "r"(a[3]), "r"(b0), "r"(b1));
}

__device__ __forceinline__ float gelu_tanh(float x) {
    float x3 = x*x*x;
    return 0.5f*x*(1.0f + tanhf(0.7978845608028654f*(x + 0.044715f*x3)));
}
__device__ __forceinline__ void split_f16(float x, __half& hi, __half& lo) {
    hi = __float2half(x);
    lo = __float2half(x - __half2float(hi));
}
__device__ __forceinline__ uint32_t swz128(int row) {
    return (uint32_t)(row*128) ^ (((uint32_t)row & 7u) << 4);
}
__device__ __forceinline__ void seg_off(int gemmid, int ks, int& aoff, int& boff) {
    if (gemmid == 0) {
        int seg = ks >> 4, ko = (ks & 15)*64;
        aoff = ko + (seg ? 1024 : 0);
        boff = ko;
    } else {
        int seg = ks >> 3, ko = (ks & 7)*64;
        aoff = seg*512 + ko;
        boff = (seg >= 2 ? 512 : 0) + ko;
    }
}

// =======================================================================
//   fp16 mma.sync GEMM (unchanged)
// =======================================================================
__global__ __launch_bounds__(512, 1)
void gemm_tc(int gemmid, float* __restrict__ outp)
{
    extern __shared__ char smem[];
    const uint32_t sb = smem_u32(smem);
    const int tid = threadIdx.x;
    const int mbase = blockIdx.y * BM;
    const int nbase = blockIdx.x * BN;
    const __half* __restrict__ Ap = gemmid ? g_a2 : g_a1;
    const __half* __restrict__ Bp = gemmid ? g_w2 : g_w1;

    float acc[2][8][4];
    #pragma unroll
    for (int i = 0; i < 2; i++)
        #pragma unroll
        for (int j = 0; j < 8; j++)
            #pragma unroll
            for (int q = 0; q < 4; q++) acc[i][j][q] = 0.f;

    const int ldA_row0 = tid >> 3,          ldA_row1 = (tid + 512) >> 3;
    const int ldB_row0 = tid >> 3,          ldB_row1 = (tid + 512) >> 3;
    const int ldB_row2 = (tid + 1024) >> 3, ldB_row3 = (tid + 1536) >> 3;
    const int ld_ch = tid & 7;
    const uint32_t chx = (uint32_t)ld_ch << 4;
    const uint32_t sA0 = swz128(ldA_row0) ^ chx;
    const uint32_t sA1 = swz128(ldA_row1) ^ chx;
    const uint32_t sB0 = (uint32_t)(BM*128) + (swz128(ldB_row0) ^ chx);
    const uint32_t sB1 = (uint32_t)(BM*128) + (swz128(ldB_row1) ^ chx);
    const uint32_t sB2 = (uint32_t)(BM*128) + (swz128(ldB_row2) ^ chx);
    const uint32_t sB3 = (uint32_t)(BM*128) + (swz128(ldB_row3) ^ chx);

    auto load_stage = [&](uint32_t sst, int aoff, int boff) {
        cpasync16(sst + sA0, Ap + (size_t)(mbase + ldA_row0)*2048 + aoff + ld_ch*8);
        cpasync16(sst + sA1, Ap + (size_t)(mbase + ldA_row1)*2048 + aoff + ld_ch*8);
        cpasync16(sst + sB0, Bp + (size_t)(nbase + ldB_row0)*1024 + boff + ld_ch*8);
        cpasync16(sst + sB1, Bp + (size_t)(nbase + ldB_row1)*1024 + boff + ld_ch*8);
        cpasync16(sst + sB2, Bp + (size_t)(nbase + ldB_row2)*1024 + boff + ld_ch*8);
        cpasync16(sst + sB3, Bp + (size_t)(nbase + ldB_row3)*1024 + boff + ld_ch*8);
    };

    const int lane = tid & 31, wid = tid >> 5;
    const int m0 = (wid & 3) * 32;
    const int n0 = (wid >> 2) * 64;

    uint32_t aBase[2], bBase[4];
    #pragma unroll
    for (int mt = 0; mt < 2; mt++)
        aBase[mt] = swz128(m0 + mt*16 + (lane & 15));
    #pragma unroll
    for (int p = 0; p < 4; p++)
        bBase[p] = (uint32_t)(BM*128) + swz128(n0 + p*16 + (lane & 15));
    const uint32_t kqSel = (uint32_t)(lane >> 4) << 4;

    auto compute_pair = [&](uint32_t sS0, uint32_t sS1) {
        uint32_t aCur[2][4], aNxt[2][4], bCur[4], bNxt[4];
        const uint32_t sArr2[2] = {sS0, sS1};
        {
            ldsm4(aCur[0], sS0 + (aBase[0] ^ kqSel));
            ldsm4(aCur[1], sS0 + (aBase[1] ^ kqSel));
            ldsm4(bCur,    sS0 + (bBase[0] ^ kqSel));
        }
        #pragma unroll
        for (int sl = 0; sl < 8; sl++) {
            uint32_t sS = sArr2[sl >> 2];
            uint32_t kx = ((uint32_t)((sl & 3) * 2) << 4) ^ kqSel;
            #pragma unroll
            for (int p = 0; p < 4; p++) {
                if (p < 3) {
                    ldsm4(bNxt, sS + (bBase[p+1] ^ kx));
                } else if (sl < 7) {
                    uint32_t sS2 = sArr2[(sl+1) >> 2];
                    uint32_t kx2 = ((uint32_t)(((sl+1) & 3) * 2) << 4) ^ kqSel;
                    ldsm4(aNxt[0], sS2 + (aBase[0] ^ kx2));
                    ldsm4(aNxt[1], sS2 + (aBase[1] ^ kx2));
                    ldsm4(bNxt,    sS2 + (bBase[0] ^ kx2));
                }
                #pragma unroll
                for (int mt = 0; mt < 2; mt++) {
                    mma_f16(acc[mt][2*p],   aCur[mt], bCur[0], bCur[2]);
                    mma_f16(acc[mt][2*p+1], aCur[mt], bCur[1], bCur[3]);
                }
                #pragma unroll
                for (int q = 0; q < 4; q++) bCur[q] = bNxt[q];
            }
            #pragma unroll
            for (int mt = 0; mt < 2; mt++)
                #pragma unroll
                for (int q = 0; q < 4; q++) aCur[mt][q] = aNxt[mt][q];
        }
    };

    {
        int ao, bo;
        seg_off(gemmid, 0, ao, bo); load_stage(sb, ao, bo); CP_COMMIT();
        seg_off(gemmid, 1, ao, bo); load_stage(sb + STAGE_BYTES, ao, bo); CP_COMMIT();
    }

    for (int ks = 0; ks < KSTEPS; ks += 2) {
        CP_WAIT0();
        __syncthreads();
        if (ks + 3 < KSTEPS) {
            int ao, bo;
            seg_off(gemmid, ks + 2, ao, bo);
            load_stage(sb + (uint32_t)(((ks + 2) & 3) * STAGE_BYTES), ao, bo);
            CP_COMMIT();
            seg_off(gemmid, ks + 3, ao, bo);
            load_stage(sb + (uint32_t)(((ks + 3) & 3) * STAGE_BYTES), ao, bo);
            CP_COMMIT();
        }
        compute_pair(sb + (uint32_t)((ks & 3) * STAGE_BYTES),
                     sb + (uint32_t)(((ks + 1) & 3) * STAGE_BYTES));
    }

    const int r_lo  = mbase + m0 + (lane >> 2);
    const int cbase = nbase + n0 + (lane & 3)*2;
    #pragma unroll
    for (int mt = 0; mt < 2; mt++) {
        #pragma unroll
        for (int nt = 0; nt < 8; nt++) {
            int col = cbase + nt*8;
            int row0 = r_lo + mt*16;
            float v0 = acc[mt][nt][0], v1 = acc[mt][nt][1];
            float v2 = acc[mt][nt][2], v3 = acc[mt][nt][3];
            if (gemmid == 0) {
                float b0 = g_bias1[col], b1 = g_bias1[col+1];
                v0 += b0; v1 += b1; v2 += b0; v3 += b1;
                int proj = col >> 9, lc = col & 511;
                if (proj < 2) {
                    v0 = gelu_tanh(v0); v1 = gelu_tanh(v1);
                    v2 = gelu_tanh(v2); v3 = gelu_tanh(v3);
                }
                float* base = g_proj + (size_t)proj * ((size_t)RR*DD);
                *reinterpret_cast<float2*>(base + (size_t)row0*DD + lc)
                    = make_float2(v0, v1);
                *reinterpret_cast<float2*>(base + (size_t)(row0+8)*DD + lc)
                    = make_float2(v2, v3);
            } else {
                float b0 = g_bias2[col], b1 = g_bias2[col+1];
                *reinterpret_cast<float2*>(outp + (size_t)row0*1024 + col)
                    = make_float2(0.5f*v0 + b0, 0.5f*v1 + b1);
                *reinterpret_cast<float2*>(outp + (size_t)(row0+8)*1024 + col)
                    = make_float2(0.5f*v2 + b0, 0.5f*v3 + b1);
            }
        }
    }
}

// =======================================================================
//   conv_main: query split (16384 blocks) + w1/bias prep (12288 blocks)
// =======================================================================
__global__ void conv_main(const float* __restrict__ query,
                          const float* __restrict__ w0, const float* __restrict__ w1,
                          const float* __restrict__ w2, const float* __restrict__ w3,
                          const float* __restrict__ w4, const float* __restrict__ w5,
                          const float* __restrict__ b0, const float* __restrict__ b1,
                          const float* __restrict__ b2, const float* __restrict__ b3,
                          const float* __restrict__ b4, const float* __restrict__ b5,
                          const float* __restrict__ bo_lin, const float* __restrict__ bo_loc)
{
    int bid = blockIdx.x;
    if (bid < 16384) {
        size_t i4 = ((size_t)bid * 256 + threadIdx.x) * 4;
        int r = (int)(i4 >> 10), c = (int)(i4 & 1023);
        float4 v = *reinterpret_cast<const float4*>(query + i4);
        __half hi[4], lo[4];
        split_f16(v.x, hi[0], lo[0]); split_f16(v.y, hi[1], lo[1]);
        split_f16(v.z, hi[2], lo[2]); split_f16(v.w, hi[3], lo[3]);
        __half* dst = g_a1 + (size_t)r*2048 + c;
        *reinterpret_cast<uint2*>(dst)        = *reinterpret_cast<uint2*>(hi);
        *reinterpret_cast<uint2*>(dst + 1024) = *reinterpret_cast<uint2*>(lo);
    } else {
        size_t i = (size_t)(bid - 16384) * 256 + threadIdx.x;   // 3072*1024
        int n = (int)(i >> 10), k = (int)(i & 1023);
        int proj = n >> 9, rloc = n & 511;
        const float* src;
        switch (proj) {
            case 0: src = w0; break; case 1: src = w1; break; case 2: src = w2; break;
            case 3: src = w3; break; case 4: src = w4; break; default: src = w5; break;
        }
        g_w1[(size_t)n*1024 + k] = __float2half(src[(size_t)rloc*1024 + k]);
        if (i < 3072) {
            int proj2 = (int)i >> 9, lc = (int)i & 511;
            const float* bs;
            switch (proj2) {
                case 0: bs = b0; break; case 1: bs = b1; break; case 2: bs = b2; break;
                case 3: bs = b3; break; case 4: bs = b4; break; default: bs = b5; break;
            }
            g_bias1[i] = bs[lc];
            if (i < 1024) g_bias2[i] = 0.5f * (bo_lin[i] + bo_loc[i]);
        }
    }
}

__global__ void conv_w2(const float* __restrict__ wo_lin, const float* __restrict__ wo_loc)
{
    size_t i = (size_t)blockIdx.x * 256 + threadIdx.x;
    int n = (int)(i >> 9), k = (int)(i & 511);
    g_w2[(size_t)n*1024 + k]       = __float2half(wo_lin[(size_t)n*512 + k]);
    g_w2[(size_t)n*1024 + 512 + k] = __float2half(wo_loc[(size_t)n*512 + k]);
}

// =======================================================================
//   attention kernels — R11 scalar register-tiled versions (48 regs)
// =======================================================================
__global__ __launch_bounds__(256)
void attn_local_kernel()
{
    __shared__ float qs[64][33];
    __shared__ float ks[64][33];
    __shared__ float vs[64][33];
    __shared__ float S [64][65];

    int z = blockIdx.x;
    int l = z & 63, h = (z >> 6) & 15, b = z >> 10;
    int tid = threadIdx.x;
    const float* Q = g_proj + (size_t)3*RR*DD;
    const float* K = g_proj + (size_t)4*RR*DD;
    const float* V = g_proj + (size_t)5*RR*DD;

    for (int idx = tid; idx < 64*32; idx += 256) {
        int c = idx >> 5, dh = idx & 31;
        size_t off = ((size_t)((l*64 + c)*BB + b))*DD + h*32 + dh;
        qs[c][dh] = Q[off]; ks[c][dh] = K[off]; vs[c][dh] = V[off];
    }
    __syncthreads();

    {
        int tr = tid >> 4, tc = tid & 15;
        int c0 = tr*4, j0 = tc*4;
        float s[4][4] = {{0.f}};
        if (tc <= tr) {
            #pragma unroll 8
            for (int d = 0; d < 32; d++) {
                float rq[4], rk[4];
                #pragma unroll
                for (int i = 0; i < 4; i++) rq[i] = qs[c0+i][d];
                #pragma unroll
                for (int j = 0; j < 4; j++) rk[j] = ks[j0+j][d];
                #pragma unroll
                for (int i = 0; i < 4; i++)
                    #pragma unroll
                    for (int j = 0; j < 4; j++)
                        s[i][j] += rq[i]*rk[j];
            }
        }
        #pragma unroll
        for (int i = 0; i < 4; i++)
            #pragma unroll
            for (int j = 0; j < 4; j++) {
                float v = (j0+j <= c0+i) ? fmaxf(s[i][j], 0.f) : 0.f;
                S[c0+i][j0+j] = v;
            }
    }
    __syncthreads();

    {
        int cg = tid >> 4, dg = tid & 15;
        int c0 = cg*4, dh0 = dg*2;
        float o[4][2] = {{0.f}};
        #pragma unroll 8
        for (int j = 0; j < 64; j++) {
            float v0 = vs[j][dh0], v1 = vs[j][dh0+1];
            #pragma unroll
            for (int i = 0; i < 4; i++) {
                float sv = S[c0+i][j];
                o[i][0] += sv*v0; o[i][1] += sv*v1;
            }
        }
        #pragma unroll
        for (int i = 0; i < 4; i++) {
            size_t off = ((size_t)((l*64 + c0+i)*BB + b))*DD + h*32 + dh0;
            *reinterpret_cast<float2*>(g_oloc + off) = make_float2(o[i][0], o[i][1]);
        }
    }
}

__global__ __launch_bounds__(256)
void attn_kv_kernel()
{
    __shared__ float ks[64][33];
    __shared__ float vs[64][33];

    int z = blockIdx.x;
    int l = z & 63, h = (z >> 6) & 15, b = z >> 10;
    int tid = threadIdx.x;
    const float* K = g_proj + (size_t)1*RR*DD;
    const float* V = g_proj + (size_t)2*RR*DD;

    for (int idx = tid; idx < 64*32; idx += 256) {
        int c = idx >> 5, dh = idx & 31;
        size_t off = ((size_t)((l*64 + c)*BB + b))*DD + h*32 + dh;
        ks[c][dh] = K[off]; vs[c][dh] = V[off];
    }
    __syncthreads();

    int d0 = (tid >> 4)*2, e0 = (tid & 15)*2;
    float s[2][2] = {{0.f}};
    #pragma unroll 8
    for (int c = 0; c < 64; c++) {
        float k0 = ks[c][d0], k1 = ks[c][d0+1];
        float v0 = vs[c][e0], v1 = vs[c][e0+1];
        s[0][0] += k0*v0; s[0][1] += k0*v1;
        s[1][0] += k1*v0; s[1][1] += k1*v1;
    }
    float* dst = g_kv + (size_t)z*1024;
    *reinterpret_cast<float2*>(dst + (d0  )*32 + e0) = make_float2(s[0][0], s[0][1]);
    *reinterpret_cast<float2*>(dst + (d0+1)*32 + e0) = make_float2(s[1][0], s[1][1]);
}

__global__ __launch_bounds__(256)
void kv_cumsum_kernel()
{
    int bh = blockIdx.x >> 2;
    int j  = (blockIdx.x & 3) * 256 + threadIdx.x;
    const float* src = g_kv     + (size_t)bh*LL*1024 + j;
    float*       dst = g_kvprev + (size_t)bh*LL*1024 + j;
    float acc = 0.f;
    #pragma unroll 8
    for (int l = 0; l < LL; l++) {
        dst[l*1024] = acc;
        acc += src[l*1024];
    }
}

__global__ __launch_bounds__(256)
void attn_lin_kernel()
{
    __shared__ float qs [64][33];
    __shared__ float ks [64][33];
    __shared__ float vs [64][33];
    __shared__ float kvp[32][33];
    __shared__ float S  [64][65];

    int z = blockIdx.x;
    int l = z & 63, h = (z >> 6) & 15, b = z >> 10;
    int tid = threadIdx.x;
    const float* Q = g_proj;
    const float* K = g_proj + (size_t)1*RR*DD;
    const float* V = g_proj + (size_t)2*RR*DD;

    for (int idx = tid; idx < 64*32; idx += 256) {
        int c = idx >> 5, dh = idx & 31;
        size_t off = ((size_t)((l*64 + c)*BB + b))*DD + h*32 + dh;
        qs[c][dh] = Q[off]; ks[c][dh] = K[off]; vs[c][dh] = V[off];
    }
    for (int idx = tid; idx < 32*32; idx += 256)
        kvp[idx >> 5][idx & 31] = g_kvprev[(size_t)z*1024 + idx];
    __syncthreads();

    {
        int tr = tid >> 4, tc = tid & 15;
        int c0 = tr*4, j0 = tc*4;
        float s[4][4] = {{0.f}};
        if (tc <= tr) {
            #pragma unroll 8
            for (int d = 0; d < 32; d++) {
                float rq[4], rk[4];
                #pragma unroll
                for (int i = 0; i < 4; i++) rq[i] = qs[c0+i][d];
                #pragma unroll
                for (int j = 0; j < 4; j++) rk[j] = ks[j0+j][d];
                #pragma unroll
                for (int i = 0; i < 4; i++)
                    #pragma unroll
                    for (int j = 0; j < 4; j++)
                        s[i][j] += rq[i]*rk[j];
            }
        }
        #pragma unroll
        for (int i = 0; i < 4; i++)
            #pragma unroll
            for (int j = 0; j < 4; j++)
                S[c0+i][j0+j] = (j0+j <= c0+i) ? s[i][j] : 0.f;
    }
    __syncthreads();

    {
        int cg = tid >> 4, dg = tid & 15;
        int c0 = cg*4, dh0 = dg*2;
        float o[4][2] = {{0.f}};
        #pragma unroll 8
        for (int j = 0; j < 64; j++) {
            float v0 = vs[j][dh0], v1 = vs[j][dh0+1];
            #pragma unroll
            for (int i = 0; i < 4; i++) {
                float sv = S[c0+i][j];
                o[i][0] += sv*v0; o[i][1] += sv*v1;
            }
        }
        #pragma unroll 8
        for (int d = 0; d < 32; d++) {
            float p0 = kvp[d][dh0], p1 = kvp[d][dh0+1];
            #pragma unroll
            for (int i = 0; i < 4; i++) {
                float qv = qs[c0+i][d];
                o[i][0] += qv*p0; o[i][1] += qv*p1;
            }
        }
        #pragma unroll
        for (int i = 0; i < 4; i++) {
            size_t off = ((size_t)((l*64 + c0+i)*BB + b))*DD + h*32 + dh0;
            *reinterpret_cast<float2*>(g_olin + off) = make_float2(o[i][0], o[i][1]);
        }
    }
}

// ---------------- norms — warp-per-row ----------------
__global__ __launch_bounds__(256)
void norm_kernel(const float* __restrict__ ln_g, const float* __restrict__ ln_b,
                 const float* __restrict__ gsc,  const float* __restrict__ ggt)
{
    int warp = (blockIdx.x << 3) | (threadIdx.x >> 5);
    int lane = threadIdx.x & 31;
    __half* a2 = g_a2 + (size_t)warp*2048;

    const float* xl = g_olin + (size_t)warp*DD;
    float xa[16];
    float sum = 0.f;
    #pragma unroll
    for (int k = 0; k < 16; k++) { xa[k] = xl[lane + 32*k]; sum += xa[k]; }
    #pragma unroll
    for (int o = 16; o > 0; o >>= 1) sum += __shfl_xor_sync(0xffffffffu, sum, o);
    float mu = sum * (1.0f/512.0f);
    float vsum = 0.f;
    #pragma unroll
    for (int k = 0; k < 16; k++) { float d = xa[k] - mu; vsum += d*d; }
    #pragma unroll
    for (int o = 16; o > 0; o >>= 1) vsum += __shfl_xor_sync(0xffffffffu, vsum, o);
    float rs = rsqrtf(vsum * (1.0f/512.0f) + 1e-5f);
    #pragma unroll
    for (int k = 0; k < 16; k++) {
        int c = lane + 32*k;
        float y = (xa[k] - mu)*rs*ln_g[c] + ln_b[c];
        __half hi, lo; split_f16(y, hi, lo);
        a2[c] = hi; a2[512 + c] = lo;
    }

    const float* xo = g_oloc + (size_t)warp*DD;
    float ms = 0.f;
    #pragma unroll
    for (int k = 0; k < 16; k++) { xa[k] = xo[lane + 32*k]; ms += xa[k]*xa[k]; }
    #pragma unroll
    for (int o = 16; o > 0; o >>= 1) ms += __shfl_xor_sync(0xffffffffu, ms, o);
    float inv = rsqrtf(ms * (1.0f/512.0f) + 1e-8f);
    #pragma unroll
    for (int k = 0; k < 16; k++) {
        int c = lane + 32*k;
        float sg = 1.0f/(1.0f + expf(-ggt[c]*xa[k]));
        float zv = xa[k]*inv*gsc[c]*sg;
        __half hi, lo; split_f16(zv, hi, lo);
        a2[1024 + c] = hi; a2[1536 + c] = lo;
    }
}

// =======================================================================
//   launch  (attn_local at idx 3 -> profiled)
// =======================================================================
extern "C" void kernel_launch(void* const* d_in, const int* in_sizes, int n_in,
                              void* d_out, int out_size)
{
    const float* query   = (const float*)d_in[0];
    const float* wq_lin  = (const float*)d_in[1];
    const float* bq_lin  = (const float*)d_in[2];
    const float* wk_lin  = (const float*)d_in[3];
    const float* bk_lin  = (const float*)d_in[4];
    const float* wv_lin  = (const float*)d_in[5];
    const float* bv_lin  = (const float*)d_in[6];
    const float* wo_lin  = (const float*)d_in[7];
    const float* bo_lin  = (const float*)d_in[8];
    const float* wq_loc  = (const float*)d_in[9];
    const float* bq_loc  = (const float*)d_in[10];
    const float* wk_loc  = (const float*)d_in[11];
    const float* bk_loc  = (const float*)d_in[12];
    const float* wv_loc  = (const float*)d_in[13];
    const float* bv_loc  = (const float*)d_in[14];
    const float* wo_loc  = (const float*)d_in[15];
    const float* bo_loc  = (const float*)d_in[16];
    const float* ln_g    = (const float*)d_in[17];
    const float* ln_b    = (const float*)d_in[18];
    const float* grn_s   = (const float*)d_in[19];
    const float* grn_g   = (const float*)d_in[20];
    float* out = (float*)d_out;

    cudaFuncSetAttribute(gemm_tc, cudaFuncAttributeMaxDynamicSharedMemorySize, SMEM_GEMM);

    // 0: fused conversions
    conv_main<<<16384 + 12288, 256>>>(query,
        wq_lin, wk_lin, wv_lin, wq_loc, wk_loc, wv_loc,
        bq_lin, bk_lin, bv_lin, bq_loc, bk_loc, bv_loc, bo_lin, bo_loc);
    // 1
    conv_w2<<<2048, 256>>>(wo_lin, wo_loc);
    // 2: fused input projections
    gemm_tc<<<dim3(3072/BN, RR/BM), 512, SMEM_GEMM>>>(0, nullptr);
    // 3: local attention (profiled)
    attn_local_kernel<<<BB*HH*LL, 256>>>();
    // 4
    attn_kv_kernel<<<BB*HH*LL, 256>>>();
    // 5
    kv_cumsum_kernel<<<BB*HH*4, 256>>>();
    // 6
    attn_lin_kernel<<<BB*HH*LL, 256>>>();
    // 7
    norm_kernel<<<RR/8, 256>>>(ln_g, ln_b, grn_s, grn_g);
    // 8: fused output projections
    gemm_tc<<<dim3(1024/BN, RR/BM), 512, SMEM_GEMM>>>(1, out);
}

// round 14
// speedup vs baseline: 1.1490x; 1.0980x over previous
#include <cuda_runtime.h>
#include <cuda_fp16.h>
#include <stdint.h>
#include <math.h>

// ---------------- problem constants ----------------
#define NN 4096
#define BB 4
#define EE 1024
#define HH 16
#define DD 512
#define DH 32
#define LL 64
#define RR (NN*BB)   // 16384 rows

// ---------------- gemm geometry ----------------
#define BM 128
#define BN 256
#define BK 64
#define STAGE_BYTES ((BM+BN)*128)   // 49152
#define NSTAGES 4
#define SMEM_GEMM (NSTAGES*STAGE_BYTES)  // 196608

// ---------------- device scratch ----------------
__device__ __half g_a1[(size_t)RR*2048];      // [query_hi | query_lo]
__device__ __half g_w1[(size_t)3072*1024];    // 6 proj weights, hi only
__device__ __half g_a2[(size_t)RR*1024];      // [ln_hi | grn_hi]  (single fp16)
__device__ __half g_w2[(size_t)1024*1024];    // [wol_hi | woc_hi]
__device__ float g_bias1[3072];
__device__ float g_bias2[1024];
__device__ float g_proj[(size_t)6*RR*DD];
__device__ float g_olin[(size_t)RR*DD];
__device__ float g_oloc[(size_t)RR*DD];
__device__ float g_kv    [(size_t)BB*HH*LL*DH*DH];
__device__ float g_kvprev[(size_t)BB*HH*LL*DH*DH];

// ---------------- asm helpers ----------
__device__ __forceinline__ uint32_t smem_u32(const void* p) {
    uint32_t a;
    asm("{ .reg .u64 t; cvta.to.shared.u64 t, %1; cvt.u32.u64 %0, t; }" : "=r"(a) : "l"(p));
    return a;
}
__device__ __forceinline__ void cpasync16(uint32_t s, const void* g) {
    asm volatile("cp.async.cg.shared.global [%0], [%1], 16;" :: "r"(s), "l"(g));
}
#define CP_COMMIT() asm volatile("cp.async.commit_group;" ::: "memory")
#define CP_WAIT0()  asm volatile("cp.async.wait_group 0;"  ::: "memory")

__device__ __forceinline__ void ldsm4(uint32_t* r, uint32_t addr) {
    asm volatile("ldmatrix.sync.aligned.m8n8.x4.shared.b16 {%0,%1,%2,%3}, [%4];"
        : "=r"(r[0]), "=r"(r[1]), "=r"(r[2]), "=r"(r[3]) : "r"(addr));
}
__device__ __forceinline__ void mma_f16(float* c, const uint32_t* a,
                                        uint32_t b0, uint32_t b1) {
    asm volatile(
        "mma.sync.aligned.m16n8k16.row.col.f32.f16.f16.f32 "
        "{%0,%1,%2,%3}, {%4,%5,%6,%7}, {%8,%9}, {%0,%1,%2,%3};"
        : "+f"(c[0]), "+f"(c[1]), "+f"(c[2]), "+f"(c[3])
        : "r"(a[0]), "r"(a[1]), "r"(a[2]), "r"(a[3]), "r"(b0), "r"(b1));
}

__device__ __forceinline__ float gelu_tanh(float x) {
    float x3 = x*x*x;
    return 0.5f*x*(1.0f + tanhf(0.7978845608028654f*(x + 0.044715f*x3)));
}
__device__ __forceinline__ void split_f16(float x, __half& hi, __half& lo) {
    hi = __float2half(x);
    lo = __float2half(x - __half2float(hi));
}
__device__ __forceinline__ uint32_t swz128(int row) {
    return (uint32_t)(row*128) ^ (((uint32_t)row & 7u) << 4);
}
// (aoff,boff) along concatenated K. gemm0: 2 segs of 1024 (q_hi,w)(q_lo,w).
// gemm1: 2 segs of 512 (ln,wol)(grn,woc).
__device__ __forceinline__ void seg_off(int gemmid, int ks, int& aoff, int& boff) {
    if (gemmid == 0) {
        int seg = ks >> 4, ko = (ks & 15)*64;
        aoff = ko + (seg ? 1024 : 0);
        boff = ko;
    } else {
        int seg = ks >> 3, ko = (ks & 7)*64;
        aoff = seg*512 + ko;
        boff = seg*512 + ko;
    }
}

// =======================================================================
//   fp16 mma.sync GEMM: runtime ksteps/astride
//   gemmid 0: K'=2048, A stride 2048  -> g_proj (+bias, gelu)
//   gemmid 1: K'=1024, A stride 1024  -> out = 0.5*acc + bias2
// =======================================================================
__global__ __launch_bounds__(512, 1)
void gemm_tc(int gemmid, int ksteps, int astride, float* __restrict__ outp)
{
    extern __shared__ char smem[];
    const uint32_t sb = smem_u32(smem);
    const int tid = threadIdx.x;
    const int mbase = blockIdx.y * BM;
    const int nbase = blockIdx.x * BN;
    const __half* __restrict__ Ap = gemmid ? g_a2 : g_a1;
    const __half* __restrict__ Bp = gemmid ? g_w2 : g_w1;

    float acc[2][8][4];
    #pragma unroll
    for (int i = 0; i < 2; i++)
        #pragma unroll
        for (int j = 0; j < 8; j++)
            #pragma unroll
            for (int q = 0; q < 4; q++) acc[i][j][q] = 0.f;

    const int ldA_row0 = tid >> 3,          ldA_row1 = (tid + 512) >> 3;
    const int ldB_row0 = tid >> 3,          ldB_row1 = (tid + 512) >> 3;
    const int ldB_row2 = (tid + 1024) >> 3, ldB_row3 = (tid + 1536) >> 3;
    const int ld_ch = tid & 7;
    const uint32_t chx = (uint32_t)ld_ch << 4;
    const uint32_t sA0 = swz128(ldA_row0) ^ chx;
    const uint32_t sA1 = swz128(ldA_row1) ^ chx;
    const uint32_t sB0 = (uint32_t)(BM*128) + (swz128(ldB_row0) ^ chx);
    const uint32_t sB1 = (uint32_t)(BM*128) + (swz128(ldB_row1) ^ chx);
    const uint32_t sB2 = (uint32_t)(BM*128) + (swz128(ldB_row2) ^ chx);
    const uint32_t sB3 = (uint32_t)(BM*128) + (swz128(ldB_row3) ^ chx);

    auto load_stage = [&](uint32_t sst, int aoff, int boff) {
        cpasync16(sst + sA0, Ap + (size_t)(mbase + ldA_row0)*astride + aoff + ld_ch*8);
        cpasync16(sst + sA1, Ap + (size_t)(mbase + ldA_row1)*astride + aoff + ld_ch*8);
        cpasync16(sst + sB0, Bp + (size_t)(nbase + ldB_row0)*1024 + boff + ld_ch*8);
        cpasync16(sst + sB1, Bp + (size_t)(nbase + ldB_row1)*1024 + boff + ld_ch*8);
        cpasync16(sst + sB2, Bp + (size_t)(nbase + ldB_row2)*1024 + boff + ld_ch*8);
        cpasync16(sst + sB3, Bp + (size_t)(nbase + ldB_row3)*1024 + boff + ld_ch*8);
    };

    const int lane = tid & 31, wid = tid >> 5;
    const int m0 = (wid & 3) * 32;
    const int n0 = (wid >> 2) * 64;

    uint32_t aBase[2], bBase[4];
    #pragma unroll
    for (int mt = 0; mt < 2; mt++)
        aBase[mt] = swz128(m0 + mt*16 + (lane & 15));
    #pragma unroll
    for (int p = 0; p < 4; p++)
        bBase[p] = (uint32_t)(BM*128) + swz128(n0 + p*16 + (lane & 15));
    const uint32_t kqSel = (uint32_t)(lane >> 4) << 4;

    auto compute_pair = [&](uint32_t sS0, uint32_t sS1) {
        uint32_t aCur[2][4], aNxt[2][4], bCur[4], bNxt[4];
        const uint32_t sArr2[2] = {sS0, sS1};
        {
            ldsm4(aCur[0], sS0 + (aBase[0] ^ kqSel));
            ldsm4(aCur[1], sS0 + (aBase[1] ^ kqSel));
            ldsm4(bCur,    sS0 + (bBase[0] ^ kqSel));
        }
        #pragma unroll
        for (int sl = 0; sl < 8; sl++) {
            uint32_t sS = sArr2[sl >> 2];
            uint32_t kx = ((uint32_t)((sl & 3) * 2) << 4) ^ kqSel;
            #pragma unroll
            for (int p = 0; p < 4; p++) {
                if (p < 3) {
                    ldsm4(bNxt, sS + (bBase[p+1] ^ kx));
                } else if (sl < 7) {
                    uint32_t sS2 = sArr2[(sl+1) >> 2];
                    uint32_t kx2 = ((uint32_t)(((sl+1) & 3) * 2) << 4) ^ kqSel;
                    ldsm4(aNxt[0], sS2 + (aBase[0] ^ kx2));
                    ldsm4(aNxt[1], sS2 + (aBase[1] ^ kx2));
                    ldsm4(bNxt,    sS2 + (bBase[0] ^ kx2));
                }
                #pragma unroll
                for (int mt = 0; mt < 2; mt++) {
                    mma_f16(acc[mt][2*p],   aCur[mt], bCur[0], bCur[2]);
                    mma_f16(acc[mt][2*p+1], aCur[mt], bCur[1], bCur[3]);
                }
                #pragma unroll
                for (int q = 0; q < 4; q++) bCur[q] = bNxt[q];
            }
            #pragma unroll
            for (int mt = 0; mt < 2; mt++)
                #pragma unroll
                for (int q = 0; q < 4; q++) aCur[mt][q] = aNxt[mt][q];
        }
    };

    {
        int ao, bo;
        seg_off(gemmid, 0, ao, bo); load_stage(sb, ao, bo); CP_COMMIT();
        seg_off(gemmid, 1, ao, bo); load_stage(sb + STAGE_BYTES, ao, bo); CP_COMMIT();
    }

    for (int ks = 0; ks < ksteps; ks += 2) {
        CP_WAIT0();
        __syncthreads();
        if (ks + 3 < ksteps) {
            int ao, bo;
            seg_off(gemmid, ks + 2, ao, bo);
            load_stage(sb + (uint32_t)(((ks + 2) & 3) * STAGE_BYTES), ao, bo);
            CP_COMMIT();
            seg_off(gemmid, ks + 3, ao, bo);
            load_stage(sb + (uint32_t)(((ks + 3) & 3) * STAGE_BYTES), ao, bo);
            CP_COMMIT();
        }
        compute_pair(sb + (uint32_t)((ks & 3) * STAGE_BYTES),
                     sb + (uint32_t)(((ks + 1) & 3) * STAGE_BYTES));
    }

    const int r_lo  = mbase + m0 + (lane >> 2);
    const int cbase = nbase + n0 + (lane & 3)*2;
    #pragma unroll
    for (int mt = 0; mt < 2; mt++) {
        #pragma unroll
        for (int nt = 0; nt < 8; nt++) {
            int col = cbase + nt*8;
            int row0 = r_lo + mt*16;
            float v0 = acc[mt][nt][0], v1 = acc[mt][nt][1];
            float v2 = acc[mt][nt][2], v3 = acc[mt][nt][3];
            if (gemmid == 0) {
                float b0 = g_bias1[col], b1 = g_bias1[col+1];
                v0 += b0; v1 += b1; v2 += b0; v3 += b1;
                int proj = col >> 9, lc = col & 511;
                if (proj < 2) {
                    v0 = gelu_tanh(v0); v1 = gelu_tanh(v1);
                    v2 = gelu_tanh(v2); v3 = gelu_tanh(v3);
                }
                float* base = g_proj + (size_t)proj * ((size_t)RR*DD);
                *reinterpret_cast<float2*>(base + (size_t)row0*DD + lc)
                    = make_float2(v0, v1);
                *reinterpret_cast<float2*>(base + (size_t)(row0+8)*DD + lc)
                    = make_float2(v2, v3);
            } else {
                float b0 = g_bias2[col], b1 = g_bias2[col+1];
                *reinterpret_cast<float2*>(outp + (size_t)row0*1024 + col)
                    = make_float2(0.5f*v0 + b0, 0.5f*v1 + b1);
                *reinterpret_cast<float2*>(outp + (size_t)(row0+8)*1024 + col)
                    = make_float2(0.5f*v2 + b0, 0.5f*v3 + b1);
            }
        }
    }
}

// =======================================================================
//   conv_main: query split + w1/bias prep + w2 prep (one launch)
// =======================================================================
__global__ void conv_main(const float* __restrict__ query,
                          const float* __restrict__ w0, const float* __restrict__ w1,
                          const float* __restrict__ w2, const float* __restrict__ w3,
                          const float* __restrict__ w4, const float* __restrict__ w5,
                          const float* __restrict__ b0, const float* __restrict__ b1,
                          const float* __restrict__ b2, const float* __restrict__ b3,
                          const float* __restrict__ b4, const float* __restrict__ b5,
                          const float* __restrict__ wo_lin, const float* __restrict__ wo_loc,
                          const float* __restrict__ bo_lin, const float* __restrict__ bo_loc)
{
    int bid = blockIdx.x;
    if (bid < 16384) {
        size_t i4 = ((size_t)bid * 256 + threadIdx.x) * 4;
        int r = (int)(i4 >> 10), c = (int)(i4 & 1023);
        float4 v = *reinterpret_cast<const float4*>(query + i4);
        __half hi[4], lo[4];
        split_f16(v.x, hi[0], lo[0]); split_f16(v.y, hi[1], lo[1]);
        split_f16(v.z, hi[2], lo[2]); split_f16(v.w, hi[3], lo[3]);
        __half* dst = g_a1 + (size_t)r*2048 + c;
        *reinterpret_cast<uint2*>(dst)        = *reinterpret_cast<uint2*>(hi);
        *reinterpret_cast<uint2*>(dst + 1024) = *reinterpret_cast<uint2*>(lo);
    } else if (bid < 16384 + 12288) {
        size_t i = (size_t)(bid - 16384) * 256 + threadIdx.x;   // 3072*1024
        int n = (int)(i >> 10), k = (int)(i & 1023);
        int proj = n >> 9, rloc = n & 511;
        const float* src;
        switch (proj) {
            case 0: src = w0; break; case 1: src = w1; break; case 2: src = w2; break;
            case 3: src = w3; break; case 4: src = w4; break; default: src = w5; break;
        }
        g_w1[(size_t)n*1024 + k] = __float2half(src[(size_t)rloc*1024 + k]);
        if (i < 3072) {
            int proj2 = (int)i >> 9, lc = (int)i & 511;
            const float* bs;
            switch (proj2) {
                case 0: bs = b0; break; case 1: bs = b1; break; case 2: bs = b2; break;
                case 3: bs = b3; break; case 4: bs = b4; break; default: bs = b5; break;
            }
            g_bias1[i] = bs[lc];
            if (i < 1024) g_bias2[i] = 0.5f * (bo_lin[i] + bo_loc[i]);
        }
    } else {
        size_t i = (size_t)(bid - 16384 - 12288) * 256 + threadIdx.x;  // 1024*512
        int n = (int)(i >> 9), k = (int)(i & 511);
        g_w2[(size_t)n*1024 + k]       = __float2half(wo_lin[(size_t)n*512 + k]);
        g_w2[(size_t)n*1024 + 512 + k] = __float2half(wo_loc[(size_t)n*512 + k]);
    }
}

// =======================================================================
//   attention kernels — scalar register-tiled (R13 versions)
// =======================================================================
__global__ __launch_bounds__(256)
void attn_local_kernel()
{
    __shared__ float qs[64][33];
    __shared__ float ks[64][33];
    __shared__ float vs[64][33];
    __shared__ float S [64][65];

    int z = blockIdx.x;
    int l = z & 63, h = (z >> 6) & 15, b = z >> 10;
    int tid = threadIdx.x;
    const float* Q = g_proj + (size_t)3*RR*DD;
    const float* K = g_proj + (size_t)4*RR*DD;
    const float* V = g_proj + (size_t)5*RR*DD;

    for (int idx = tid; idx < 64*32; idx += 256) {
        int c = idx >> 5, dh = idx & 31;
        size_t off = ((size_t)((l*64 + c)*BB + b))*DD + h*32 + dh;
        qs[c][dh] = Q[off]; ks[c][dh] = K[off]; vs[c][dh] = V[off];
    }
    __syncthreads();

    {
        int tr = tid >> 4, tc = tid & 15;
        int c0 = tr*4, j0 = tc*4;
        float s[4][4] = {{0.f}};
        if (tc <= tr) {
            #pragma unroll 8
            for (int d = 0; d < 32; d++) {
                float rq[4], rk[4];
                #pragma unroll
                for (int i = 0; i < 4; i++) rq[i] = qs[c0+i][d];
                #pragma unroll
                for (int j = 0; j < 4; j++) rk[j] = ks[j0+j][d];
                #pragma unroll
                for (int i = 0; i < 4; i++)
                    #pragma unroll
                    for (int j = 0; j < 4; j++)
                        s[i][j] += rq[i]*rk[j];
            }
        }
        #pragma unroll
        for (int i = 0; i < 4; i++)
            #pragma unroll
            for (int j = 0; j < 4; j++) {
                float v = (j0+j <= c0+i) ? fmaxf(s[i][j], 0.f) : 0.f;
                S[c0+i][j0+j] = v;
            }
    }
    __syncthreads();

    {
        int cg = tid >> 4, dg = tid & 15;
        int c0 = cg*4, dh0 = dg*2;
        float o[4][2] = {{0.f}};
        #pragma unroll 8
        for (int j = 0; j < 64; j++) {
            float v0 = vs[j][dh0], v1 = vs[j][dh0+1];
            #pragma unroll
            for (int i = 0; i < 4; i++) {
                float sv = S[c0+i][j];
                o[i][0] += sv*v0; o[i][1] += sv*v1;
            }
        }
        #pragma unroll
        for (int i = 0; i < 4; i++) {
            size_t off = ((size_t)((l*64 + c0+i)*BB + b))*DD + h*32 + dh0;
            *reinterpret_cast<float2*>(g_oloc + off) = make_float2(o[i][0], o[i][1]);
        }
    }
}

__global__ __launch_bounds__(256)
void attn_kv_kernel()
{
    __shared__ float ks[64][33];
    __shared__ float vs[64][33];

    int z = blockIdx.x;
    int l = z & 63, h = (z >> 6) & 15, b = z >> 10;
    int tid = threadIdx.x;
    const float* K = g_proj + (size_t)1*RR*DD;
    const float* V = g_proj + (size_t)2*RR*DD;

    for (int idx = tid; idx < 64*32; idx += 256) {
        int c = idx >> 5, dh = idx & 31;
        size_t off = ((size_t)((l*64 + c)*BB + b))*DD + h*32 + dh;
        ks[c][dh] = K[off]; vs[c][dh] = V[off];
    }
    __syncthreads();

    int d0 = (tid >> 4)*2, e0 = (tid & 15)*2;
    float s[2][2] = {{0.f}};
    #pragma unroll 8
    for (int c = 0; c < 64; c++) {
        float k0 = ks[c][d0], k1 = ks[c][d0+1];
        float v0 = vs[c][e0], v1 = vs[c][e0+1];
        s[0][0] += k0*v0; s[0][1] += k0*v1;
        s[1][0] += k1*v0; s[1][1] += k1*v1;
    }
    float* dst = g_kv + (size_t)z*1024;
    *reinterpret_cast<float2*>(dst + (d0  )*32 + e0) = make_float2(s[0][0], s[0][1]);
    *reinterpret_cast<float2*>(dst + (d0+1)*32 + e0) = make_float2(s[1][0], s[1][1]);
}

__global__ __launch_bounds__(256)
void kv_cumsum_kernel()
{
    int bh = blockIdx.x >> 2;
    int j  = (blockIdx.x & 3) * 256 + threadIdx.x;
    const float* src = g_kv     + (size_t)bh*LL*1024 + j;
    float*       dst = g_kvprev + (size_t)bh*LL*1024 + j;
    float acc = 0.f;
    #pragma unroll 8
    for (int l = 0; l < LL; l++) {
        dst[l*1024] = acc;
        acc += src[l*1024];
    }
}

__global__ __launch_bounds__(256)
void attn_lin_kernel()
{
    __shared__ float qs [64][33];
    __shared__ float ks [64][33];
    __shared__ float vs [64][33];
    __shared__ float kvp[32][33];
    __shared__ float S  [64][65];

    int z = blockIdx.x;
    int l = z & 63, h = (z >> 6) & 15, b = z >> 10;
    int tid = threadIdx.x;
    const float* Q = g_proj;
    const float* K = g_proj + (size_t)1*RR*DD;
    const float* V = g_proj + (size_t)2*RR*DD;

    for (int idx = tid; idx < 64*32; idx += 256) {
        int c = idx >> 5, dh = idx & 31;
        size_t off = ((size_t)((l*64 + c)*BB + b))*DD + h*32 + dh;
        qs[c][dh] = Q[off]; ks[c][dh] = K[off]; vs[c][dh] = V[off];
    }
    for (int idx = tid; idx < 32*32; idx += 256)
        kvp[idx >> 5][idx & 31] = g_kvprev[(size_t)z*1024 + idx];
    __syncthreads();

    {
        int tr = tid >> 4, tc = tid & 15;
        int c0 = tr*4, j0 = tc*4;
        float s[4][4] = {{0.f}};
        if (tc <= tr) {
            #pragma unroll 8
            for (int d = 0; d < 32; d++) {
                float rq[4], rk[4];
                #pragma unroll
                for (int i = 0; i < 4; i++) rq[i] = qs[c0+i][d];
                #pragma unroll
                for (int j = 0; j < 4; j++) rk[j] = ks[j0+j][d];
                #pragma unroll
                for (int i = 0; i < 4; i++)
                    #pragma unroll
                    for (int j = 0; j < 4; j++)
                        s[i][j] += rq[i]*rk[j];
            }
        }
        #pragma unroll
        for (int i = 0; i < 4; i++)
            #pragma unroll
            for (int j = 0; j < 4; j++)
                S[c0+i][j0+j] = (j0+j <= c0+i) ? s[i][j] : 0.f;
    }
    __syncthreads();

    {
        int cg = tid >> 4, dg = tid & 15;
        int c0 = cg*4, dh0 = dg*2;
        float o[4][2] = {{0.f}};
        #pragma unroll 8
        for (int j = 0; j < 64; j++) {
            float v0 = vs[j][dh0], v1 = vs[j][dh0+1];
            #pragma unroll
            for (int i = 0; i < 4; i++) {
                float sv = S[c0+i][j];
                o[i][0] += sv*v0; o[i][1] += sv*v1;
            }
        }
        #pragma unroll 8
        for (int d = 0; d < 32; d++) {
            float p0 = kvp[d][dh0], p1 = kvp[d][dh0+1];
            #pragma unroll
            for (int i = 0; i < 4; i++) {
                float qv = qs[c0+i][d];
                o[i][0] += qv*p0; o[i][1] += qv*p1;
            }
        }
        #pragma unroll
        for (int i = 0; i < 4; i++) {
            size_t off = ((size_t)((l*64 + c0+i)*BB + b))*DD + h*32 + dh0;
            *reinterpret_cast<float2*>(g_olin + off) = make_float2(o[i][0], o[i][1]);
        }
    }
}

// ---------------- norms — warp-per-row, single fp16 output ----------------
__global__ __launch_bounds__(256)
void norm_kernel(const float* __restrict__ ln_g, const float* __restrict__ ln_b,
                 const float* __restrict__ gsc,  const float* __restrict__ ggt)
{
    int warp = (blockIdx.x << 3) | (threadIdx.x >> 5);
    int lane = threadIdx.x & 31;
    __half* a2 = g_a2 + (size_t)warp*1024;

    const float* xl = g_olin + (size_t)warp*DD;
    float xa[16];
    float sum = 0.f;
    #pragma unroll
    for (int k = 0; k < 16; k++) { xa[k] = xl[lane + 32*k]; sum += xa[k]; }
    #pragma unroll
    for (int o = 16; o > 0; o >>= 1) sum += __shfl_xor_sync(0xffffffffu, sum, o);
    float mu = sum * (1.0f/512.0f);
    float vsum = 0.f;
    #pragma unroll
    for (int k = 0; k < 16; k++) { float d = xa[k] - mu; vsum += d*d; }
    #pragma unroll
    for (int o = 16; o > 0; o >>= 1) vsum += __shfl_xor_sync(0xffffffffu, vsum, o);
    float rs = rsqrtf(vsum * (1.0f/512.0f) + 1e-5f);
    #pragma unroll
    for (int k = 0; k < 16; k++) {
        int c = lane + 32*k;
        a2[c] = __float2half((xa[k] - mu)*rs*ln_g[c] + ln_b[c]);
    }

    const float* xo = g_oloc + (size_t)warp*DD;
    float ms = 0.f;
    #pragma unroll
    for (int k = 0; k < 16; k++) { xa[k] = xo[lane + 32*k]; ms += xa[k]*xa[k]; }
    #pragma unroll
    for (int o = 16; o > 0; o >>= 1) ms += __shfl_xor_sync(0xffffffffu, ms, o);
    float inv = rsqrtf(ms * (1.0f/512.0f) + 1e-8f);
    #pragma unroll
    for (int k = 0; k < 16; k++) {
        int c = lane + 32*k;
        float sg = 1.0f/(1.0f + expf(-ggt[c]*xa[k]));
        a2[512 + c] = __float2half(xa[k]*inv*gsc[c]*sg);
    }
}

// =======================================================================
//   launch
// =======================================================================
extern "C" void kernel_launch(void* const* d_in, const int* in_sizes, int n_in,
                              void* d_out, int out_size)
{
    const float* query   = (const float*)d_in[0];
    const float* wq_lin  = (const float*)d_in[1];
    const float* bq_lin  = (const float*)d_in[2];
    const float* wk_lin  = (const float*)d_in[3];
    const float* bk_lin  = (const float*)d_in[4];
    const float* wv_lin  = (const float*)d_in[5];
    const float* bv_lin  = (const float*)d_in[6];
    const float* wo_lin  = (const float*)d_in[7];
    const float* bo_lin  = (const float*)d_in[8];
    const float* wq_loc  = (const float*)d_in[9];
    const float* bq_loc  = (const float*)d_in[10];
    const float* wk_loc  = (const float*)d_in[11];
    const float* bk_loc  = (const float*)d_in[12];
    const float* wv_loc  = (const float*)d_in[13];
    const float* bv_loc  = (const float*)d_in[14];
    const float* wo_loc  = (const float*)d_in[15];
    const float* bo_loc  = (const float*)d_in[16];
    const float* ln_g    = (const float*)d_in[17];
    const float* ln_b    = (const float*)d_in[18];
    const float* grn_s   = (const float*)d_in[19];
    const float* grn_g   = (const float*)d_in[20];
    float* out = (float*)d_out;

    cudaFuncSetAttribute(gemm_tc, cudaFuncAttributeMaxDynamicSharedMemorySize, SMEM_GEMM);

    // 0: all conversions (query split + w1/biases + w2)
    conv_main<<<16384 + 12288 + 2048, 256>>>(query,
        wq_lin, wk_lin, wv_lin, wq_loc, wk_loc, wv_loc,
        bq_lin, bk_lin, bv_lin, bq_loc, bk_loc, bv_loc,
        wo_lin, wo_loc, bo_lin, bo_loc);
    // 1: fused input projections (K'=2048)
    gemm_tc<<<dim3(3072/BN, RR/BM), 512, SMEM_GEMM>>>(0, 32, 2048, nullptr);
    // 2
    attn_local_kernel<<<BB*HH*LL, 256>>>();
    // 3: (profiled)
    attn_kv_kernel<<<BB*HH*LL, 256>>>();
    // 4
    kv_cumsum_kernel<<<BB*HH*4, 256>>>();
    // 5
    attn_lin_kernel<<<BB*HH*LL, 256>>>();
    // 6
    norm_kernel<<<RR/8, 256>>>(ln_g, ln_b, grn_s, grn_g);
    // 7: fused output projections (K'=1024, single-fp16 A)
    gemm_tc<<<dim3(1024/BN, RR/BM), 512, SMEM_GEMM>>>(1, 16, 1024, out);
}

// round 16
// speedup vs baseline: 1.5340x; 1.3351x over previous
#include <cuda_runtime.h>
#include <cuda_fp16.h>
#include <stdint.h>
#include <math.h>

// ---------------- problem constants ----------------
#define NN 4096
#define BB 4
#define EE 1024
#define HH 16
#define DD 512
#define DH 32
#define LL 64
#define RR (NN*BB)   // 16384 rows

// ---------------- gemm geometry ----------------
#define BM 128
#define BN 256
#define BK 64
#define KSTEPS 16                   // both gemms: K' = 1024, plain fp16
#define STAGE_BYTES ((BM+BN)*128)   // 49152
#define NSTAGES 4
#define SMEM_GEMM (NSTAGES*STAGE_BYTES)  // 196608

// ---------------- device scratch ----------------
__device__ __half g_a1[(size_t)RR*1024];      // query (fp16)
__device__ __half g_w1[(size_t)3072*1024];    // 6 proj weights (fp16)
__device__ __half g_a2[(size_t)RR*1024];      // [ln | grn]  (fp16)
__device__ __half g_w2[(size_t)1024*1024];    // [wol | woc] (fp16)
__device__ float g_bias1[3072];
__device__ float g_bias2[1024];
__device__ float g_proj[(size_t)6*RR*DD];
__device__ float g_olin[(size_t)RR*DD];
__device__ float g_oloc[(size_t)RR*DD];
__device__ float g_kv    [(size_t)BB*HH*LL*DH*DH];
__device__ float g_kvprev[(size_t)BB*HH*LL*DH*DH];

// ---------------- asm helpers ----------
__device__ __forceinline__ uint32_t smem_u32(const void* p) {
    uint32_t a;
    asm("{ .reg .u64 t; cvta.to.shared.u64 t, %1; cvt.u32.u64 %0, t; }" : "=r"(a) : "l"(p));
    return a;
}
__device__ __forceinline__ void cpasync16(uint32_t s, const void* g) {
    asm volatile("cp.async.cg.shared.global [%0], [%1], 16;" :: "r"(s), "l"(g));
}
#define CP_COMMIT() asm volatile("cp.async.commit_group;" ::: "memory")
#define CP_WAIT0()  asm volatile("cp.async.wait_group 0;"  ::: "memory")

__device__ __forceinline__ void ldsm4(uint32_t* r, uint32_t addr) {
    asm volatile("ldmatrix.sync.aligned.m8n8.x4.shared.b16 {%0,%1,%2,%3}, [%4];"
        : "=r"(r[0]), "=r"(r[1]), "=r"(r[2]), "=r"(r[3]) : "r"(addr));
}
__device__ __forceinline__ void mma_f16(float* c, const uint32_t* a,
                                        uint32_t b0, uint32_t b1) {
    asm volatile(
        "mma.sync.aligned.m16n8k16.row.col.f32.f16.f16.f32 "
        "{%0,%1,%2,%3}, {%4,%5,%6,%7}, {%8,%9}, {%0,%1,%2,%3};"
        : "+f"(c[0]), "+f"(c[1]), "+f"(c[2]), "+f"(c[3])
        : "r"(a[0]), "r"(a[1]), "r"(a[2]), "r"(a[3]), "r"(b0), "r"(b1));
}

__device__ __forceinline__ float gelu_tanh(float x) {
    float x3 = x*x*x;
    return 0.5f*x*(1.0f + tanhf(0.7978845608028654f*(x + 0.044715f*x3)));
}
__device__ __forceinline__ uint32_t swz128(int row) {
    return (uint32_t)(row*128) ^ (((uint32_t)row & 7u) << 4);
}

// =======================================================================
//   fp16 mma.sync GEMM: K'=1024, A/B stride 1024, 512 thr, 4 stages
//   gemmid 0: N=3072 -> g_proj (+bias, gelu on first two projections)
//   gemmid 1: N=1024 -> out = 0.5*acc + bias2
// =======================================================================
__global__ __launch_bounds__(512, 1)
void gemm_tc(int gemmid, float* __restrict__ outp)
{
    extern __shared__ char smem[];
    const uint32_t sb = smem_u32(smem);
    const int tid = threadIdx.x;
    const int mbase = blockIdx.y * BM;
    const int nbase = blockIdx.x * BN;
    const __half* __restrict__ Ap = gemmid ? g_a2 : g_a1;
    const __half* __restrict__ Bp = gemmid ? g_w2 : g_w1;

    float acc[2][8][4];
    #pragma unroll
    for (int i = 0; i < 2; i++)
        #pragma unroll
        for (int j = 0; j < 8; j++)
            #pragma unroll
            for (int q = 0; q < 4; q++) acc[i][j][q] = 0.f;

    const int ldA_row0 = tid >> 3,          ldA_row1 = (tid + 512) >> 3;
    const int ldB_row0 = tid >> 3,          ldB_row1 = (tid + 512) >> 3;
    const int ldB_row2 = (tid + 1024) >> 3, ldB_row3 = (tid + 1536) >> 3;
    const int ld_ch = tid & 7;
    const uint32_t chx = (uint32_t)ld_ch << 4;
    const uint32_t sA0 = swz128(ldA_row0) ^ chx;
    const uint32_t sA1 = swz128(ldA_row1) ^ chx;
    const uint32_t sB0 = (uint32_t)(BM*128) + (swz128(ldB_row0) ^ chx);
    const uint32_t sB1 = (uint32_t)(BM*128) + (swz128(ldB_row1) ^ chx);
    const uint32_t sB2 = (uint32_t)(BM*128) + (swz128(ldB_row2) ^ chx);
    const uint32_t sB3 = (uint32_t)(BM*128) + (swz128(ldB_row3) ^ chx);

    auto load_stage = [&](uint32_t sst, int ko) {
        cpasync16(sst + sA0, Ap + (size_t)(mbase + ldA_row0)*1024 + ko + ld_ch*8);
        cpasync16(sst + sA1, Ap + (size_t)(mbase + ldA_row1)*1024 + ko + ld_ch*8);
        cpasync16(sst + sB0, Bp + (size_t)(nbase + ldB_row0)*1024 + ko + ld_ch*8);
        cpasync16(sst + sB1, Bp + (size_t)(nbase + ldB_row1)*1024 + ko + ld_ch*8);
        cpasync16(sst + sB2, Bp + (size_t)(nbase + ldB_row2)*1024 + ko + ld_ch*8);
        cpasync16(sst + sB3, Bp + (size_t)(nbase + ldB_row3)*1024 + ko + ld_ch*8);
    };

    const int lane = tid & 31, wid = tid >> 5;
    const int m0 = (wid & 3) * 32;
    const int n0 = (wid >> 2) * 64;

    uint32_t aBase[2], bBase[4];
    #pragma unroll
    for (int mt = 0; mt < 2; mt++)
        aBase[mt] = swz128(m0 + mt*16 + (lane & 15));
    #pragma unroll
    for (int p = 0; p < 4; p++)
        bBase[p] = (uint32_t)(BM*128) + swz128(n0 + p*16 + (lane & 15));
    const uint32_t kqSel = (uint32_t)(lane >> 4) << 4;

    auto compute_pair = [&](uint32_t sS0, uint32_t sS1) {
        uint32_t aCur[2][4], aNxt[2][4], bCur[4], bNxt[4];
        const uint32_t sArr2[2] = {sS0, sS1};
        {
            ldsm4(aCur[0], sS0 + (aBase[0] ^ kqSel));
            ldsm4(aCur[1], sS0 + (aBase[1] ^ kqSel));
            ldsm4(bCur,    sS0 + (bBase[0] ^ kqSel));
        }
        #pragma unroll
        for (int sl = 0; sl < 8; sl++) {
            uint32_t sS = sArr2[sl >> 2];
            uint32_t kx = ((uint32_t)((sl & 3) * 2) << 4) ^ kqSel;
            #pragma unroll
            for (int p = 0; p < 4; p++) {
                if (p < 3) {
                    ldsm4(bNxt, sS + (bBase[p+1] ^ kx));
                } else if (sl < 7) {
                    uint32_t sS2 = sArr2[(sl+1) >> 2];
                    uint32_t kx2 = ((uint32_t)(((sl+1) & 3) * 2) << 4) ^ kqSel;
                    ldsm4(aNxt[0], sS2 + (aBase[0] ^ kx2));
                    ldsm4(aNxt[1], sS2 + (aBase[1] ^ kx2));
                    ldsm4(bNxt,    sS2 + (bBase[0] ^ kx2));
                }
                #pragma unroll
                for (int mt = 0; mt < 2; mt++) {
                    mma_f16(acc[mt][2*p],   aCur[mt], bCur[0], bCur[2]);
                    mma_f16(acc[mt][2*p+1], aCur[mt], bCur[1], bCur[3]);
                }
                #pragma unroll
                for (int q = 0; q < 4; q++) bCur[q] = bNxt[q];
            }
            #pragma unroll
            for (int mt = 0; mt < 2; mt++)
                #pragma unroll
                for (int q = 0; q < 4; q++) aCur[mt][q] = aNxt[mt][q];
        }
    };

    load_stage(sb, 0); CP_COMMIT();
    load_stage(sb + STAGE_BYTES, 64); CP_COMMIT();

    for (int ks = 0; ks < KSTEPS; ks += 2) {
        CP_WAIT0();
        __syncthreads();
        if (ks + 3 < KSTEPS) {
            load_stage(sb + (uint32_t)(((ks + 2) & 3) * STAGE_BYTES), (ks + 2)*64);
            CP_COMMIT();
            load_stage(sb + (uint32_t)(((ks + 3) & 3) * STAGE_BYTES), (ks + 3)*64);
            CP_COMMIT();
        }
        compute_pair(sb + (uint32_t)((ks & 3) * STAGE_BYTES),
                     sb + (uint32_t)(((ks + 1) & 3) * STAGE_BYTES));
    }

    const int r_lo  = mbase + m0 + (lane >> 2);
    const int cbase = nbase + n0 + (lane & 3)*2;
    #pragma unroll
    for (int mt = 0; mt < 2; mt++) {
        #pragma unroll
        for (int nt = 0; nt < 8; nt++) {
            int col = cbase + nt*8;
            int row0 = r_lo + mt*16;
            float v0 = acc[mt][nt][0], v1 = acc[mt][nt][1];
            float v2 = acc[mt][nt][2], v3 = acc[mt][nt][3];
            if (gemmid == 0) {
                float b0 = g_bias1[col], b1 = g_bias1[col+1];
                v0 += b0; v1 += b1; v2 += b0; v3 += b1;
                int proj = col >> 9, lc = col & 511;
                if (proj < 2) {
                    v0 = gelu_tanh(v0); v1 = gelu_tanh(v1);
                    v2 = gelu_tanh(v2); v3 = gelu_tanh(v3);
                }
                float* base = g_proj + (size_t)proj * ((size_t)RR*DD);
                *reinterpret_cast<float2*>(base + (size_t)row0*DD + lc)
                    = make_float2(v0, v1);
                *reinterpret_cast<float2*>(base + (size_t)(row0+8)*DD + lc)
                    = make_float2(v2, v3);
            } else {
                float b0 = g_bias2[col], b1 = g_bias2[col+1];
                *reinterpret_cast<float2*>(outp + (size_t)row0*1024 + col)
                    = make_float2(0.5f*v0 + b0, 0.5f*v1 + b1);
                *reinterpret_cast<float2*>(outp + (size_t)(row0+8)*1024 + col)
                    = make_float2(0.5f*v2 + b0, 0.5f*v3 + b1);
            }
        }
    }
}

// =======================================================================
//   conv_main: query fp16 (4096 blocks) + w1/bias (12288) + w2 (2048)
// =======================================================================
__global__ void conv_main(const float* __restrict__ query,
                          const float* __restrict__ w0, const float* __restrict__ w1,
                          const float* __restrict__ w2, const float* __restrict__ w3,
                          const float* __restrict__ w4, const float* __restrict__ w5,
                          const float* __restrict__ b0, const float* __restrict__ b1,
                          const float* __restrict__ b2, const float* __restrict__ b3,
                          const float* __restrict__ b4, const float* __restrict__ b5,
                          const float* __restrict__ wo_lin, const float* __restrict__ wo_loc,
                          const float* __restrict__ bo_lin, const float* __restrict__ bo_loc)
{
    int bid = blockIdx.x;
    if (bid < 4096) {
        // query -> fp16, 16 elems/thread
        size_t i16 = ((size_t)bid * 256 + threadIdx.x) * 16;
        #pragma unroll
        for (int u = 0; u < 4; u++) {
            float4 v = *reinterpret_cast<const float4*>(query + i16 + u*4);
            __half h[4];
            h[0] = __float2half(v.x); h[1] = __float2half(v.y);
            h[2] = __float2half(v.z); h[3] = __float2half(v.w);
            *reinterpret_cast<uint2*>(g_a1 + i16 + u*4) = *reinterpret_cast<uint2*>(h);
        }
    } else if (bid < 4096 + 12288) {
        size_t i = (size_t)(bid - 4096) * 256 + threadIdx.x;   // 3072*1024
        int n = (int)(i >> 10), k = (int)(i & 1023);
        int proj = n >> 9, rloc = n & 511;
        const float* src;
        switch (proj) {
            case 0: src = w0; break; case 1: src = w1; break; case 2: src = w2; break;
            case 3: src = w3; break; case 4: src = w4; break; default: src = w5; break;
        }
        g_w1[(size_t)n*1024 + k] = __float2half(src[(size_t)rloc*1024 + k]);
        if (i < 3072) {
            int proj2 = (int)i >> 9, lc = (int)i & 511;
            const float* bs;
            switch (proj2) {
                case 0: bs = b0; break; case 1: bs = b1; break; case 2: bs = b2; break;
                case 3: bs = b3; break; case 4: bs = b4; break; default: bs = b5; break;
            }
            g_bias1[i] = bs[lc];
            if (i < 1024) g_bias2[i] = 0.5f * (bo_lin[i] + bo_loc[i]);
        }
    } else {
        size_t i = (size_t)(bid - 4096 - 12288) * 256 + threadIdx.x;  // 1024*512
        int n = (int)(i >> 9), k = (int)(i & 511);
        g_w2[(size_t)n*1024 + k]       = __float2half(wo_lin[(size_t)n*512 + k]);
        g_w2[(size_t)n*1024 + 512 + k] = __float2half(wo_loc[(size_t)n*512 + k]);
    }
}

// =======================================================================
//   attention kernels — scalar register-tiled
// =======================================================================
__global__ __launch_bounds__(256)
void attn_local_kernel()
{
    __shared__ float qs[64][33];
    __shared__ float ks[64][33];
    __shared__ float vs[64][33];
    __shared__ float S [64][65];

    int z = blockIdx.x;
    int l = z & 63, h = (z >> 6) & 15, b = z >> 10;
    int tid = threadIdx.x;
    const float* Q = g_proj + (size_t)3*RR*DD;
    const float* K = g_proj + (size_t)4*RR*DD;
    const float* V = g_proj + (size_t)5*RR*DD;

    for (int idx = tid; idx < 64*32; idx += 256) {
        int c = idx >> 5, dh = idx & 31;
        size_t off = ((size_t)((l*64 + c)*BB + b))*DD + h*32 + dh;
        qs[c][dh] = Q[off]; ks[c][dh] = K[off]; vs[c][dh] = V[off];
    }
    __syncthreads();

    {
        int tr = tid >> 4, tc = tid & 15;
        int c0 = tr*4, j0 = tc*4;
        float s[4][4] = {{0.f}};
        if (tc <= tr) {
            #pragma unroll 8
            for (int d = 0; d < 32; d++) {
                float rq[4], rk[4];
                #pragma unroll
                for (int i = 0; i < 4; i++) rq[i] = qs[c0+i][d];
                #pragma unroll
                for (int j = 0; j < 4; j++) rk[j] = ks[j0+j][d];
                #pragma unroll
                for (int i = 0; i < 4; i++)
                    #pragma unroll
                    for (int j = 0; j < 4; j++)
                        s[i][j] += rq[i]*rk[j];
            }
        }
        #pragma unroll
        for (int i = 0; i < 4; i++)
            #pragma unroll
            for (int j = 0; j < 4; j++) {
                float v = (j0+j <= c0+i) ? fmaxf(s[i][j], 0.f) : 0.f;
                S[c0+i][j0+j] = v;
            }
    }
    __syncthreads();

    {
        int cg = tid >> 4, dg = tid & 15;
        int c0 = cg*4, dh0 = dg*2;
        float o[4][2] = {{0.f}};
        #pragma unroll 8
        for (int j = 0; j < 64; j++) {
            float v0 = vs[j][dh0], v1 = vs[j][dh0+1];
            #pragma unroll
            for (int i = 0; i < 4; i++) {
                float sv = S[c0+i][j];
                o[i][0] += sv*v0; o[i][1] += sv*v1;
            }
        }
        #pragma unroll
        for (int i = 0; i < 4; i++) {
            size_t off = ((size_t)((l*64 + c0+i)*BB + b))*DD + h*32 + dh0;
            *reinterpret_cast<float2*>(g_oloc + off) = make_float2(o[i][0], o[i][1]);
        }
    }
}

__global__ __launch_bounds__(256)
void attn_kv_kernel()
{
    __shared__ float ks[64][33];
    __shared__ float vs[64][33];

    int z = blockIdx.x;
    int l = z & 63, h = (z >> 6) & 15, b = z >> 10;
    int tid = threadIdx.x;
    const float* K = g_proj + (size_t)1*RR*DD;
    const float* V = g_proj + (size_t)2*RR*DD;

    for (int idx = tid; idx < 64*32; idx += 256) {
        int c = idx >> 5, dh = idx & 31;
        size_t off = ((size_t)((l*64 + c)*BB + b))*DD + h*32 + dh;
        ks[c][dh] = K[off]; vs[c][dh] = V[off];
    }
    __syncthreads();

    int d0 = (tid >> 4)*2, e0 = (tid & 15)*2;
    float s[2][2] = {{0.f}};
    #pragma unroll 8
    for (int c = 0; c < 64; c++) {
        float k0 = ks[c][d0], k1 = ks[c][d0+1];
        float v0 = vs[c][e0], v1 = vs[c][e0+1];
        s[0][0] += k0*v0; s[0][1] += k0*v1;
        s[1][0] += k1*v0; s[1][1] += k1*v1;
    }
    float* dst = g_kv + (size_t)z*1024;
    *reinterpret_cast<float2*>(dst + (d0  )*32 + e0) = make_float2(s[0][0], s[0][1]);
    *reinterpret_cast<float2*>(dst + (d0+1)*32 + e0) = make_float2(s[1][0], s[1][1]);
}

__global__ __launch_bounds__(256)
void kv_cumsum_kernel()
{
    int bh = blockIdx.x >> 2;
    int j  = (blockIdx.x & 3) * 256 + threadIdx.x;
    const float* src = g_kv     + (size_t)bh*LL*1024 + j;
    float*       dst = g_kvprev + (size_t)bh*LL*1024 + j;
    float acc = 0.f;
    #pragma unroll 8
    for (int l = 0; l < LL; l++) {
        dst[l*1024] = acc;
        acc += src[l*1024];
    }
}

__global__ __launch_bounds__(256)
void attn_lin_kernel()
{
    __shared__ float qs [64][33];
    __shared__ float ks [64][33];
    __shared__ float vs [64][33];
    __shared__ float kvp[32][33];
    __shared__ float S  [64][65];

    int z = blockIdx.x;
    int l = z & 63, h = (z >> 6) & 15, b = z >> 10;
    int tid = threadIdx.x;
    const float* Q = g_proj;
    const float* K = g_proj + (size_t)1*RR*DD;
    const float* V = g_proj + (size_t)2*RR*DD;

    for (int idx = tid; idx < 64*32; idx += 256) {
        int c = idx >> 5, dh = idx & 31;
        size_t off = ((size_t)((l*64 + c)*BB + b))*DD + h*32 + dh;
        qs[c][dh] = Q[off]; ks[c][dh] = K[off]; vs[c][dh] = V[off];
    }
    for (int idx = tid; idx < 32*32; idx += 256)
        kvp[idx >> 5][idx & 31] = g_kvprev[(size_t)z*1024 + idx];
    __syncthreads();

    {
        int tr = tid >> 4, tc = tid & 15;
        int c0 = tr*4, j0 = tc*4;
        float s[4][4] = {{0.f}};
        if (tc <= tr) {
            #pragma unroll 8
            for (int d = 0; d < 32; d++) {
                float rq[4], rk[4];
                #pragma unroll
                for (int i = 0; i < 4; i++) rq[i] = qs[c0+i][d];
                #pragma unroll
                for (int j = 0; j < 4; j++) rk[j] = ks[j0+j][d];
                #pragma unroll
                for (int i = 0; i < 4; i++)
                    #pragma unroll
                    for (int j = 0; j < 4; j++)
                        s[i][j] += rq[i]*rk[j];
            }
        }
        #pragma unroll
        for (int i = 0; i < 4; i++)
            #pragma unroll
            for (int j = 0; j < 4; j++)
                S[c0+i][j0+j] = (j0+j <= c0+i) ? s[i][j] : 0.f;
    }
    __syncthreads();

    {
        int cg = tid >> 4, dg = tid & 15;
        int c0 = cg*4, dh0 = dg*2;
        float o[4][2] = {{0.f}};
        #pragma unroll 8
        for (int j = 0; j < 64; j++) {
            float v0 = vs[j][dh0], v1 = vs[j][dh0+1];
            #pragma unroll
            for (int i = 0; i < 4; i++) {
                float sv = S[c0+i][j];
                o[i][0] += sv*v0; o[i][1] += sv*v1;
            }
        }
        #pragma unroll 8
        for (int d = 0; d < 32; d++) {
            float p0 = kvp[d][dh0], p1 = kvp[d][dh0+1];
            #pragma unroll
            for (int i = 0; i < 4; i++) {
                float qv = qs[c0+i][d];
                o[i][0] += qv*p0; o[i][1] += qv*p1;
            }
        }
        #pragma unroll
        for (int i = 0; i < 4; i++) {
            size_t off = ((size_t)((l*64 + c0+i)*BB + b))*DD + h*32 + dh0;
            *reinterpret_cast<float2*>(g_olin + off) = make_float2(o[i][0], o[i][1]);
        }
    }
}

// ---------------- norms — warp-per-row, fp16 outputs ----------------
__global__ __launch_bounds__(256)
void norm_kernel(const float* __restrict__ ln_g, const float* __restrict__ ln_b,
                 const float* __restrict__ gsc,  const float* __restrict__ ggt)
{
    int warp = (blockIdx.x << 3) | (threadIdx.x >> 5);
    int lane = threadIdx.x & 31;
    __half* a2 = g_a2 + (size_t)warp*1024;

    const float* xl = g_olin + (size_t)warp*DD;
    float xa[16];
    float sum = 0.f;
    #pragma unroll
    for (int k = 0; k < 16; k++) { xa[k] = xl[lane + 32*k]; sum += xa[k]; }
    #pragma unroll
    for (int o = 16; o > 0; o >>= 1) sum += __shfl_xor_sync(0xffffffffu, sum, o);
    float mu = sum * (1.0f/512.0f);
    float vsum = 0.f;
    #pragma unroll
    for (int k = 0; k < 16; k++) { float d = xa[k] - mu; vsum += d*d; }
    #pragma unroll
    for (int o = 16; o > 0; o >>= 1) vsum += __shfl_xor_sync(0xffffffffu, vsum, o);
    float rs = rsqrtf(vsum * (1.0f/512.0f) + 1e-5f);
    #pragma unroll
    for (int k = 0; k < 16; k++) {
        int c = lane + 32*k;
        a2[c] = __float2half((xa[k] - mu)*rs*ln_g[c] + ln_b[c]);
    }

    const float* xo = g_oloc + (size_t)warp*DD;
    float ms = 0.f;
    #pragma unroll
    for (int k = 0; k < 16; k++) { xa[k] = xo[lane + 32*k]; ms += xa[k]*xa[k]; }
    #pragma unroll
    for (int o = 16; o > 0; o >>= 1) ms += __shfl_xor_sync(0xffffffffu, ms, o);
    float inv = rsqrtf(ms * (1.0f/512.0f) + 1e-8f);
    #pragma unroll
    for (int k = 0; k < 16; k++) {
        int c = lane + 32*k;
        float sg = 1.0f/(1.0f + expf(-ggt[c]*xa[k]));
        a2[512 + c] = __float2half(xa[k]*inv*gsc[c]*sg);
    }
}

// =======================================================================
//   launch
// =======================================================================
extern "C" void kernel_launch(void* const* d_in, const int* in_sizes, int n_in,
                              void* d_out, int out_size)
{
    const float* query   = (const float*)d_in[0];
    const float* wq_lin  = (const float*)d_in[1];
    const float* bq_lin  = (const float*)d_in[2];
    const float* wk_lin  = (const float*)d_in[3];
    const float* bk_lin  = (const float*)d_in[4];
    const float* wv_lin  = (const float*)d_in[5];
    const float* bv_lin  = (const float*)d_in[6];
    const float* wo_lin  = (const float*)d_in[7];
    const float* bo_lin  = (const float*)d_in[8];
    const float* wq_loc  = (const float*)d_in[9];
    const float* bq_loc  = (const float*)d_in[10];
    const float* wk_loc  = (const float*)d_in[11];
    const float* bk_loc  = (const float*)d_in[12];
    const float* wv_loc  = (const float*)d_in[13];
    const float* bv_loc  = (const float*)d_in[14];
    const float* wo_loc  = (const float*)d_in[15];
    const float* bo_loc  = (const float*)d_in[16];
    const float* ln_g    = (const float*)d_in[17];
    const float* ln_b    = (const float*)d_in[18];
    const float* grn_s   = (const float*)d_in[19];
    const float* grn_g   = (const float*)d_in[20];
    float* out = (float*)d_out;

    cudaFuncSetAttribute(gemm_tc, cudaFuncAttributeMaxDynamicSharedMemorySize, SMEM_GEMM);

    // 0: all conversions
    conv_main<<<4096 + 12288 + 2048, 256>>>(query,
        wq_lin, wk_lin, wv_lin, wq_loc, wk_loc, wv_loc,
        bq_lin, bk_lin, bv_lin, bq_loc, bk_loc, bv_loc,
        wo_lin, wo_loc, bo_lin, bo_loc);
    // 1: fused input projections (K'=1024)
    gemm_tc<<<dim3(3072/BN, RR/BM), 512, SMEM_GEMM>>>(0, nullptr);
    // 2
    attn_local_kernel<<<BB*HH*LL, 256>>>();
    // 3: (profiled)
    attn_kv_kernel<<<BB*HH*LL, 256>>>();
    // 4
    kv_cumsum_kernel<<<BB*HH*4, 256>>>();
    // 5
    attn_lin_kernel<<<BB*HH*LL, 256>>>();
    // 6
    norm_kernel<<<RR/8, 256>>>(ln_g, ln_b, grn_s, grn_g);
    // 7: fused output projections (K'=1024)
    gemm_tc<<<dim3(1024/BN, RR/BM), 512, SMEM_GEMM>>>(1, out);
}

// round 17
// speedup vs baseline: 1.5382x; 1.0027x over previous
#include <cuda_runtime.h>
#include <cuda_fp16.h>
#include <stdint.h>
#include <math.h>

// ---------------- problem constants ----------------
#define NN 4096
#define BB 4
#define EE 1024
#define HH 16
#define DD 512
#define DH 32
#define LL 64
#define RR (NN*BB)   // 16384 rows

// ---------------- gemm geometry ----------------
#define BM 128
#define BN 256
#define BK 64
#define KSTEPS 16                   // both gemms: K' = 1024, plain fp16
#define STAGE_BYTES ((BM+BN)*128)   // 49152
#define NSTAGES 4
#define SMEM_GEMM (NSTAGES*STAGE_BYTES)  // 196608

// ---------------- device scratch ----------------
__device__ __half g_a1[(size_t)RR*1024];      // query (fp16)
__device__ __half g_w1[(size_t)3072*1024];    // 6 proj weights (fp16)
__device__ __half g_a2[(size_t)RR*1024];      // [ln | grn]  (fp16)
__device__ __half g_w2[(size_t)1024*1024];    // [wol | woc] (fp16)
__device__ float g_bias1[3072];
__device__ float g_bias2[1024];
__device__ float g_proj[(size_t)6*RR*DD];
__device__ float g_olin[(size_t)RR*DD];
__device__ float g_oloc[(size_t)RR*DD];
__device__ float g_kv    [(size_t)BB*HH*LL*DH*DH];
__device__ float g_kvprev[(size_t)BB*HH*LL*DH*DH];

// ---------------- asm helpers ----------
__device__ __forceinline__ uint32_t smem_u32(const void* p) {
    uint32_t a;
    asm("{ .reg .u64 t; cvta.to.shared.u64 t, %1; cvt.u32.u64 %0, t; }" : "=r"(a) : "l"(p));
    return a;
}
__device__ __forceinline__ void cpasync16(uint32_t s, const void* g) {
    asm volatile("cp.async.cg.shared.global [%0], [%1], 16;" :: "r"(s), "l"(g));
}
#define CP_COMMIT() asm volatile("cp.async.commit_group;" ::: "memory")
#define CP_WAIT0()  asm volatile("cp.async.wait_group 0;"  ::: "memory")

__device__ __forceinline__ void ldsm4(uint32_t* r, uint32_t addr) {
    asm volatile("ldmatrix.sync.aligned.m8n8.x4.shared.b16 {%0,%1,%2,%3}, [%4];"
        : "=r"(r[0]), "=r"(r[1]), "=r"(r[2]), "=r"(r[3]) : "r"(addr));
}
__device__ __forceinline__ void mma_f16(float* c, const uint32_t* a,
                                        uint32_t b0, uint32_t b1) {
    asm volatile(
        "mma.sync.aligned.m16n8k16.row.col.f32.f16.f16.f32 "
        "{%0,%1,%2,%3}, {%4,%5,%6,%7}, {%8,%9}, {%0,%1,%2,%3};"
        : "+f"(c[0]), "+f"(c[1]), "+f"(c[2]), "+f"(c[3])
        : "r"(a[0]), "r"(a[1]), "r"(a[2]), "r"(a[3]), "r"(b0), "r"(b1));
}

__device__ __forceinline__ float gelu_tanh(float x) {
    float x3 = x*x*x;
    return 0.5f*x*(1.0f + tanhf(0.7978845608028654f*(x + 0.044715f*x3)));
}
__device__ __forceinline__ uint32_t swz128(int row) {
    return (uint32_t)(row*128) ^ (((uint32_t)row & 7u) << 4);
}

// =======================================================================
//   fp16 mma.sync GEMM: K'=1024, A/B stride 1024, 512 thr, 4 stages
//   gemmid 0: N=3072 -> g_proj (+bias, gelu on first two projections)
//   gemmid 1: N=1024 -> out = 0.5*acc + bias2
// =======================================================================
__global__ __launch_bounds__(512, 1)
void gemm_tc(int gemmid, float* __restrict__ outp)
{
    extern __shared__ char smem[];
    const uint32_t sb = smem_u32(smem);
    const int tid = threadIdx.x;
    const int mbase = blockIdx.y * BM;
    const int nbase = blockIdx.x * BN;
    const __half* __restrict__ Ap = gemmid ? g_a2 : g_a1;
    const __half* __restrict__ Bp = gemmid ? g_w2 : g_w1;

    float acc[2][8][4];
    #pragma unroll
    for (int i = 0; i < 2; i++)
        #pragma unroll
        for (int j = 0; j < 8; j++)
            #pragma unroll
            for (int q = 0; q < 4; q++) acc[i][j][q] = 0.f;

    const int ldA_row0 = tid >> 3,          ldA_row1 = (tid + 512) >> 3;
    const int ldB_row0 = tid >> 3,          ldB_row1 = (tid + 512) >> 3;
    const int ldB_row2 = (tid + 1024) >> 3, ldB_row3 = (tid + 1536) >> 3;
    const int ld_ch = tid & 7;
    const uint32_t chx = (uint32_t)ld_ch << 4;
    const uint32_t sA0 = swz128(ldA_row0) ^ chx;
    const uint32_t sA1 = swz128(ldA_row1) ^ chx;
    const uint32_t sB0 = (uint32_t)(BM*128) + (swz128(ldB_row0) ^ chx);
    const uint32_t sB1 = (uint32_t)(BM*128) + (swz128(ldB_row1) ^ chx);
    const uint32_t sB2 = (uint32_t)(BM*128) + (swz128(ldB_row2) ^ chx);
    const uint32_t sB3 = (uint32_t)(BM*128) + (swz128(ldB_row3) ^ chx);

    auto load_stage = [&](uint32_t sst, int ko) {
        cpasync16(sst + sA0, Ap + (size_t)(mbase + ldA_row0)*1024 + ko + ld_ch*8);
        cpasync16(sst + sA1, Ap + (size_t)(mbase + ldA_row1)*1024 + ko + ld_ch*8);
        cpasync16(sst + sB0, Bp + (size_t)(nbase + ldB_row0)*1024 + ko + ld_ch*8);
        cpasync16(sst + sB1, Bp + (size_t)(nbase + ldB_row1)*1024 + ko + ld_ch*8);
        cpasync16(sst + sB2, Bp + (size_t)(nbase + ldB_row2)*1024 + ko + ld_ch*8);
        cpasync16(sst + sB3, Bp + (size_t)(nbase + ldB_row3)*1024 + ko + ld_ch*8);
    };

    const int lane = tid & 31, wid = tid >> 5;
    const int m0 = (wid & 3) * 32;
    const int n0 = (wid >> 2) * 64;

    uint32_t aBase[2], bBase[4];
    #pragma unroll
    for (int mt = 0; mt < 2; mt++)
        aBase[mt] = swz128(m0 + mt*16 + (lane & 15));
    #pragma unroll
    for (int p = 0; p < 4; p++)
        bBase[p] = (uint32_t)(BM*128) + swz128(n0 + p*16 + (lane & 15));
    const uint32_t kqSel = (uint32_t)(lane >> 4) << 4;

    auto compute_pair = [&](uint32_t sS0, uint32_t sS1) {
        uint32_t aCur[2][4], aNxt[2][4], bCur[4], bNxt[4];
        const uint32_t sArr2[2] = {sS0, sS1};
        {
            ldsm4(aCur[0], sS0 + (aBase[0] ^ kqSel));
            ldsm4(aCur[1], sS0 + (aBase[1] ^ kqSel));
            ldsm4(bCur,    sS0 + (bBase[0] ^ kqSel));
        }
        #pragma unroll
        for (int sl = 0; sl < 8; sl++) {
            uint32_t sS = sArr2[sl >> 2];
            uint32_t kx = ((uint32_t)((sl & 3) * 2) << 4) ^ kqSel;
            #pragma unroll
            for (int p = 0; p < 4; p++) {
                if (p < 3) {
                    ldsm4(bNxt, sS + (bBase[p+1] ^ kx));
                } else if (sl < 7) {
                    uint32_t sS2 = sArr2[(sl+1) >> 2];
                    uint32_t kx2 = ((uint32_t)(((sl+1) & 3) * 2) << 4) ^ kqSel;
                    ldsm4(aNxt[0], sS2 + (aBase[0] ^ kx2));
                    ldsm4(aNxt[1], sS2 + (aBase[1] ^ kx2));
                    ldsm4(bNxt,    sS2 + (bBase[0] ^ kx2));
                }
                #pragma unroll
                for (int mt = 0; mt < 2; mt++) {
                    mma_f16(acc[mt][2*p],   aCur[mt], bCur[0], bCur[2]);
                    mma_f16(acc[mt][2*p+1], aCur[mt], bCur[1], bCur[3]);
                }
                #pragma unroll
                for (int q = 0; q < 4; q++) bCur[q] = bNxt[q];
            }
            #pragma unroll
            for (int mt = 0; mt < 2; mt++)
                #pragma unroll
                for (int q = 0; q < 4; q++) aCur[mt][q] = aNxt[mt][q];
        }
    };

    load_stage(sb, 0); CP_COMMIT();
    load_stage(sb + STAGE_BYTES, 64); CP_COMMIT();

    for (int ks = 0; ks < KSTEPS; ks += 2) {
        CP_WAIT0();
        __syncthreads();
        if (ks + 3 < KSTEPS) {
            load_stage(sb + (uint32_t)(((ks + 2) & 3) * STAGE_BYTES), (ks + 2)*64);
            CP_COMMIT();
            load_stage(sb + (uint32_t)(((ks + 3) & 3) * STAGE_BYTES), (ks + 3)*64);
            CP_COMMIT();
        }
        compute_pair(sb + (uint32_t)((ks & 3) * STAGE_BYTES),
                     sb + (uint32_t)(((ks + 1) & 3) * STAGE_BYTES));
    }

    const int r_lo  = mbase + m0 + (lane >> 2);
    const int cbase = nbase + n0 + (lane & 3)*2;
    #pragma unroll
    for (int mt = 0; mt < 2; mt++) {
        #pragma unroll
        for (int nt = 0; nt < 8; nt++) {
            int col = cbase + nt*8;
            int row0 = r_lo + mt*16;
            float v0 = acc[mt][nt][0], v1 = acc[mt][nt][1];
            float v2 = acc[mt][nt][2], v3 = acc[mt][nt][3];
            if (gemmid == 0) {
                float b0 = g_bias1[col], b1 = g_bias1[col+1];
                v0 += b0; v1 += b1; v2 += b0; v3 += b1;
                int proj = col >> 9, lc = col & 511;
                if (proj < 2) {
                    v0 = gelu_tanh(v0); v1 = gelu_tanh(v1);
                    v2 = gelu_tanh(v2); v3 = gelu_tanh(v3);
                }
                float* base = g_proj + (size_t)proj * ((size_t)RR*DD);
                *reinterpret_cast<float2*>(base + (size_t)row0*DD + lc)
                    = make_float2(v0, v1);
                *reinterpret_cast<float2*>(base + (size_t)(row0+8)*DD + lc)
                    = make_float2(v2, v3);
            } else {
                float b0 = g_bias2[col], b1 = g_bias2[col+1];
                *reinterpret_cast<float2*>(outp + (size_t)row0*1024 + col)
                    = make_float2(0.5f*v0 + b0, 0.5f*v1 + b1);
                *reinterpret_cast<float2*>(outp + (size_t)(row0+8)*1024 + col)
                    = make_float2(0.5f*v2 + b0, 0.5f*v3 + b1);
            }
        }
    }
}

// =======================================================================
//   conv_main: query fp16 (4096 blocks) + w1/bias (12288) + w2 (2048)
// =======================================================================
__global__ void conv_main(const float* __restrict__ query,
                          const float* __restrict__ w0, const float* __restrict__ w1,
                          const float* __restrict__ w2, const float* __restrict__ w3,
                          const float* __restrict__ w4, const float* __restrict__ w5,
                          const float* __restrict__ b0, const float* __restrict__ b1,
                          const float* __restrict__ b2, const float* __restrict__ b3,
                          const float* __restrict__ b4, const float* __restrict__ b5,
                          const float* __restrict__ wo_lin, const float* __restrict__ wo_loc,
                          const float* __restrict__ bo_lin, const float* __restrict__ bo_loc)
{
    int bid = blockIdx.x;
    if (bid < 4096) {
        // query -> fp16, 16 elems/thread
        size_t i16 = ((size_t)bid * 256 + threadIdx.x) * 16;
        #pragma unroll
        for (int u = 0; u < 4; u++) {
            float4 v = *reinterpret_cast<const float4*>(query + i16 + u*4);
            __half h[4];
            h[0] = __float2half(v.x); h[1] = __float2half(v.y);
            h[2] = __float2half(v.z); h[3] = __float2half(v.w);
            *reinterpret_cast<uint2*>(g_a1 + i16 + u*4) = *reinterpret_cast<uint2*>(h);
        }
    } else if (bid < 4096 + 12288) {
        size_t i = (size_t)(bid - 4096) * 256 + threadIdx.x;   // 3072*1024
        int n = (int)(i >> 10), k = (int)(i & 1023);
        int proj = n >> 9, rloc = n & 511;
        const float* src;
        switch (proj) {
            case 0: src = w0; break; case 1: src = w1; break; case 2: src = w2; break;
            case 3: src = w3; break; case 4: src = w4; break; default: src = w5; break;
        }
        g_w1[(size_t)n*1024 + k] = __float2half(src[(size_t)rloc*1024 + k]);
        if (i < 3072) {
            int proj2 = (int)i >> 9, lc = (int)i & 511;
            const float* bs;
            switch (proj2) {
                case 0: bs = b0; break; case 1: bs = b1; break; case 2: bs = b2; break;
                case 3: bs = b3; break; case 4: bs = b4; break; default: bs = b5; break;
            }
            g_bias1[i] = bs[lc];
            if (i < 1024) g_bias2[i] = 0.5f * (bo_lin[i] + bo_loc[i]);
        }
    } else {
        size_t i = (size_t)(bid - 4096 - 12288) * 256 + threadIdx.x;  // 1024*512
        int n = (int)(i >> 9), k = (int)(i & 511);
        g_w2[(size_t)n*1024 + k]       = __float2half(wo_lin[(size_t)n*512 + k]);
        g_w2[(size_t)n*1024 + 512 + k] = __float2half(wo_loc[(size_t)n*512 + k]);
    }
}

// =======================================================================
//   attention kernels — scalar register-tiled
// =======================================================================
__global__ __launch_bounds__(256)
void attn_local_kernel()
{
    __shared__ float qs[64][33];
    __shared__ float ks[64][33];
    __shared__ float vs[64][33];
    __shared__ float S [64][65];

    int z = blockIdx.x;
    int l = z & 63, h = (z >> 6) & 15, b = z >> 10;
    int tid = threadIdx.x;
    const float* Q = g_proj + (size_t)3*RR*DD;
    const float* K = g_proj + (size_t)4*RR*DD;
    const float* V = g_proj + (size_t)5*RR*DD;

    for (int idx = tid; idx < 64*32; idx += 256) {
        int c = idx >> 5, dh = idx & 31;
        size_t off = ((size_t)((l*64 + c)*BB + b))*DD + h*32 + dh;
        qs[c][dh] = Q[off]; ks[c][dh] = K[off]; vs[c][dh] = V[off];
    }
    __syncthreads();

    {
        int tr = tid >> 4, tc = tid & 15;
        int c0 = tr*4, j0 = tc*4;
        float s[4][4] = {{0.f}};
        if (tc <= tr) {
            #pragma unroll 8
            for (int d = 0; d < 32; d++) {
                float rq[4], rk[4];
                #pragma unroll
                for (int i = 0; i < 4; i++) rq[i] = qs[c0+i][d];
                #pragma unroll
                for (int j = 0; j < 4; j++) rk[j] = ks[j0+j][d];
                #pragma unroll
                for (int i = 0; i < 4; i++)
                    #pragma unroll
                    for (int j = 0; j < 4; j++)
                        s[i][j] += rq[i]*rk[j];
            }
        }
        #pragma unroll
        for (int i = 0; i < 4; i++)
            #pragma unroll
            for (int j = 0; j < 4; j++) {
                float v = (j0+j <= c0+i) ? fmaxf(s[i][j], 0.f) : 0.f;
                S[c0+i][j0+j] = v;
            }
    }
    __syncthreads();

    {
        int cg = tid >> 4, dg = tid & 15;
        int c0 = cg*4, dh0 = dg*2;
        float o[4][2] = {{0.f}};
        #pragma unroll 8
        for (int j = 0; j < 64; j++) {
            float v0 = vs[j][dh0], v1 = vs[j][dh0+1];
            #pragma unroll
            for (int i = 0; i < 4; i++) {
                float sv = S[c0+i][j];
                o[i][0] += sv*v0; o[i][1] += sv*v1;
            }
        }
        #pragma unroll
        for (int i = 0; i < 4; i++) {
            size_t off = ((size_t)((l*64 + c0+i)*BB + b))*DD + h*32 + dh0;
            *reinterpret_cast<float2*>(g_oloc + off) = make_float2(o[i][0], o[i][1]);
        }
    }
}

__global__ __launch_bounds__(256)
void attn_kv_kernel()
{
    __shared__ float ks[64][33];
    __shared__ float vs[64][33];

    int z = blockIdx.x;
    int l = z & 63, h = (z >> 6) & 15, b = z >> 10;
    int tid = threadIdx.x;
    const float* K = g_proj + (size_t)1*RR*DD;
    const float* V = g_proj + (size_t)2*RR*DD;

    for (int idx = tid; idx < 64*32; idx += 256) {
        int c = idx >> 5, dh = idx & 31;
        size_t off = ((size_t)((l*64 + c)*BB + b))*DD + h*32 + dh;
        ks[c][dh] = K[off]; vs[c][dh] = V[off];
    }
    __syncthreads();

    int d0 = (tid >> 4)*2, e0 = (tid & 15)*2;
    float s[2][2] = {{0.f}};
    #pragma unroll 8
    for (int c = 0; c < 64; c++) {
        float k0 = ks[c][d0], k1 = ks[c][d0+1];
        float v0 = vs[c][e0], v1 = vs[c][e0+1];
        s[0][0] += k0*v0; s[0][1] += k0*v1;
        s[1][0] += k1*v0; s[1][1] += k1*v1;
    }
    float* dst = g_kv + (size_t)z*1024;
    *reinterpret_cast<float2*>(dst + (d0  )*32 + e0) = make_float2(s[0][0], s[0][1]);
    *reinterpret_cast<float2*>(dst + (d0+1)*32 + e0) = make_float2(s[1][0], s[1][1]);
}

__global__ __launch_bounds__(256)
void kv_cumsum_kernel()
{
    int bh = blockIdx.x >> 2;
    int j  = (blockIdx.x & 3) * 256 + threadIdx.x;
    const float* src = g_kv     + (size_t)bh*LL*1024 + j;
    float*       dst = g_kvprev + (size_t)bh*LL*1024 + j;
    float acc = 0.f;
    #pragma unroll 8
    for (int l = 0; l < LL; l++) {
        dst[l*1024] = acc;
        acc += src[l*1024];
    }
}

__global__ __launch_bounds__(256)
void attn_lin_kernel()
{
    __shared__ float qs [64][33];
    __shared__ float ks [64][33];
    __shared__ float vs [64][33];
    __shared__ float kvp[32][33];
    __shared__ float S  [64][65];

    int z = blockIdx.x;
    int l = z & 63, h = (z >> 6) & 15, b = z >> 10;
    int tid = threadIdx.x;
    const float* Q = g_proj;
    const float* K = g_proj + (size_t)1*RR*DD;
    const float* V = g_proj + (size_t)2*RR*DD;

    for (int idx = tid; idx < 64*32; idx += 256) {
        int c = idx >> 5, dh = idx & 31;
        size_t off = ((size_t)((l*64 + c)*BB + b))*DD + h*32 + dh;
        qs[c][dh] = Q[off]; ks[c][dh] = K[off]; vs[c][dh] = V[off];
    }
    for (int idx = tid; idx < 32*32; idx += 256)
        kvp[idx >> 5][idx & 31] = g_kvprev[(size_t)z*1024 + idx];
    __syncthreads();

    {
        int tr = tid >> 4, tc = tid & 15;
        int c0 = tr*4, j0 = tc*4;
        float s[4][4] = {{0.f}};
        if (tc <= tr) {
            #pragma unroll 8
            for (int d = 0; d < 32; d++) {
                float rq[4], rk[4];
                #pragma unroll
                for (int i = 0; i < 4; i++) rq[i] = qs[c0+i][d];
                #pragma unroll
                for (int j = 0; j < 4; j++) rk[j] = ks[j0+j][d];
                #pragma unroll
                for (int i = 0; i < 4; i++)
                    #pragma unroll
                    for (int j = 0; j < 4; j++)
                        s[i][j] += rq[i]*rk[j];
            }
        }
        #pragma unroll
        for (int i = 0; i < 4; i++)
            #pragma unroll
            for (int j = 0; j < 4; j++)
                S[c0+i][j0+j] = (j0+j <= c0+i) ? s[i][j] : 0.f;
    }
    __syncthreads();

    {
        int cg = tid >> 4, dg = tid & 15;
        int c0 = cg*4, dh0 = dg*2;
        float o[4][2] = {{0.f}};
        #pragma unroll 8
        for (int j = 0; j < 64; j++) {
            float v0 = vs[j][dh0], v1 = vs[j][dh0+1];
            #pragma unroll
            for (int i = 0; i < 4; i++) {
                float sv = S[c0+i][j];
                o[i][0] += sv*v0; o[i][1] += sv*v1;
            }
        }
        #pragma unroll 8
        for (int d = 0; d < 32; d++) {
            float p0 = kvp[d][dh0], p1 = kvp[d][dh0+1];
            #pragma unroll
            for (int i = 0; i < 4; i++) {
                float qv = qs[c0+i][d];
                o[i][0] += qv*p0; o[i][1] += qv*p1;
            }
        }
        #pragma unroll
        for (int i = 0; i < 4; i++) {
            size_t off = ((size_t)((l*64 + c0+i)*BB + b))*DD + h*32 + dh0;
            *reinterpret_cast<float2*>(g_olin + off) = make_float2(o[i][0], o[i][1]);
        }
    }
}

// ---------------- norms — warp-per-row, fp16 outputs ----------------
__global__ __launch_bounds__(256)
void norm_kernel(const float* __restrict__ ln_g, const float* __restrict__ ln_b,
                 const float* __restrict__ gsc,  const float* __restrict__ ggt)
{
    int warp = (blockIdx.x << 3) | (threadIdx.x >> 5);
    int lane = threadIdx.x & 31;
    __half* a2 = g_a2 + (size_t)warp*1024;

    const float* xl = g_olin + (size_t)warp*DD;
    float xa[16];
    float sum = 0.f;
    #pragma unroll
    for (int k = 0; k < 16; k++) { xa[k] = xl[lane + 32*k]; sum += xa[k]; }
    #pragma unroll
    for (int o = 16; o > 0; o >>= 1) sum += __shfl_xor_sync(0xffffffffu, sum, o);
    float mu = sum * (1.0f/512.0f);
    float vsum = 0.f;
    #pragma unroll
    for (int k = 0; k < 16; k++) { float d = xa[k] - mu; vsum += d*d; }
    #pragma unroll
    for (int o = 16; o > 0; o >>= 1) vsum += __shfl_xor_sync(0xffffffffu, vsum, o);
    float rs = rsqrtf(vsum * (1.0f/512.0f) + 1e-5f);
    #pragma unroll
    for (int k = 0; k < 16; k++) {
        int c = lane + 32*k;
        a2[c] = __float2half((xa[k] - mu)*rs*ln_g[c] + ln_b[c]);
    }

    const float* xo = g_oloc + (size_t)warp*DD;
    float ms = 0.f;
    #pragma unroll
    for (int k = 0; k < 16; k++) { xa[k] = xo[lane + 32*k]; ms += xa[k]*xa[k]; }
    #pragma unroll
    for (int o = 16; o > 0; o >>= 1) ms += __shfl_xor_sync(0xffffffffu, ms, o);
    float inv = rsqrtf(ms * (1.0f/512.0f) + 1e-8f);
    #pragma unroll
    for (int k = 0; k < 16; k++) {
        int c = lane + 32*k;
        float sg = 1.0f/(1.0f + expf(-ggt[c]*xa[k]));
        a2[512 + c] = __float2half(xa[k]*inv*gsc[c]*sg);
    }
}

// =======================================================================
//   launch
// =======================================================================
extern "C" void kernel_launch(void* const* d_in, const int* in_sizes, int n_in,
                              void* d_out, int out_size)
{
    const float* query   = (const float*)d_in[0];
    const float* wq_lin  = (const float*)d_in[1];
    const float* bq_lin  = (const float*)d_in[2];
    const float* wk_lin  = (const float*)d_in[3];
    const float* bk_lin  = (const float*)d_in[4];
    const float* wv_lin  = (const float*)d_in[5];
    const float* bv_lin  = (const float*)d_in[6];
    const float* wo_lin  = (const float*)d_in[7];
    const float* bo_lin  = (const float*)d_in[8];
    const float* wq_loc  = (const float*)d_in[9];
    const float* bq_loc  = (const float*)d_in[10];
    const float* wk_loc  = (const float*)d_in[11];
    const float* bk_loc  = (const float*)d_in[12];
    const float* wv_loc  = (const float*)d_in[13];
    const float* bv_loc  = (const float*)d_in[14];
    const float* wo_loc  = (const float*)d_in[15];
    const float* bo_loc  = (const float*)d_in[16];
    const float* ln_g    = (const float*)d_in[17];
    const float* ln_b    = (const float*)d_in[18];
    const float* grn_s   = (const float*)d_in[19];
    const float* grn_g   = (const float*)d_in[20];
    float* out = (float*)d_out;

    cudaFuncSetAttribute(gemm_tc, cudaFuncAttributeMaxDynamicSharedMemorySize, SMEM_GEMM);

    // 0: all conversions
    conv_main<<<4096 + 12288 + 2048, 256>>>(query,
        wq_lin, wk_lin, wv_lin, wq_loc, wk_loc, wv_loc,
        bq_lin, bk_lin, bv_lin, bq_loc, bk_loc, bv_loc,
        wo_lin, wo_loc, bo_lin, bo_loc);
    // 1: fused input projections (K'=1024)
    gemm_tc<<<dim3(3072/BN, RR/BM), 512, SMEM_GEMM>>>(0, nullptr);
    // 2
    attn_local_kernel<<<BB*HH*LL, 256>>>();
    // 3: (profiled)
    attn_kv_kernel<<<BB*HH*LL, 256>>>();
    // 4
    kv_cumsum_kernel<<<BB*HH*4, 256>>>();
    // 5
    attn_lin_kernel<<<BB*HH*LL, 256>>>();
    // 6
    norm_kernel<<<RR/8, 256>>>(ln_g, ln_b, grn_s, grn_g);
    // 7: fused output projections (K'=1024)
    gemm_tc<<<dim3(1024/BN, RR/BM), 512, SMEM_GEMM>>>(1, out);
}